// round 4
// baseline (speedup 1.0000x reference)
#include <cuda_runtime.h>
#include <math.h>

// Problem constants
#define B_   2
#define T_   2048
#define C_   2048
#define H_   32
#define HK_  4
#define D_   64
#define MROWS (B_ * T_)          // 4096

// ---------------- scratch (static device globals; no allocation) ----------
__device__ float g_qraw[(long long)MROWS * (H_ * D_)];   // (B*T, 2048) raw q proj
__device__ float g_kraw[(long long)MROWS * (HK_ * D_)];  // (B*T, 256)
__device__ float g_vraw[(long long)MROWS * (HK_ * D_)];  // (B*T, 256)
__device__ float g_q   [(long long)B_ * H_ * T_ * D_];   // (B,H,T,D) roped+scaled
__device__ float g_o   [(long long)MROWS * (H_ * D_)];   // (B,T,H*D) attention out

// ===========================================================================
// GEMM:  C[M,N] = A[M,K] @ W[N,K]^T   (A, W row-major)
// Tile: BM=128, BN=64, BK=32. 256 threads, 8x4 micro-tile per thread.
// ===========================================================================
#define BM 128
#define BN 64
#define BK 32
#define AS_STR (BM + 4)   // 132 (mult of 4 for float4 reads, 4-way STS worst)
#define WS_STR (BN + 4)   // 68

__global__ __launch_bounds__(256)
void gemm_nt(const float* __restrict__ A, const float* __restrict__ W,
             float* __restrict__ Cout, int M, int N, int K)
{
    __shared__ float As[BK][AS_STR];
    __shared__ float Ws[BK][WS_STR];

    const int tid = threadIdx.x;
    const int tx  = tid & 15;     // column group (0..15) -> 4 cols
    const int ty  = tid >> 4;     // row group    (0..15) -> 8 rows
    const int bm  = blockIdx.y * BM;
    const int bn  = blockIdx.x * BN;

    float acc[8][4];
#pragma unroll
    for (int i = 0; i < 8; i++)
#pragma unroll
        for (int j = 0; j < 4; j++) acc[i][j] = 0.f;

    for (int k0 = 0; k0 < K; k0 += BK) {
        // Load A tile 128x32 (1024 float4, 4 per thread), transpose to As[k][m]
#pragma unroll
        for (int r = 0; r < 4; r++) {
            int e  = tid + r * 256;
            int m  = e >> 3;          // 0..127
            int kc = e & 7;           // 0..7 (float4 chunk of k)
            float4 v = *(const float4*)(A + (size_t)(bm + m) * K + k0 + kc * 4);
            As[kc * 4 + 0][m] = v.x;
            As[kc * 4 + 1][m] = v.y;
            As[kc * 4 + 2][m] = v.z;
            As[kc * 4 + 3][m] = v.w;
        }
        // Load W tile 64x32 (512 float4, 2 per thread), transpose to Ws[k][n]
#pragma unroll
        for (int r = 0; r < 2; r++) {
            int e  = tid + r * 256;
            int n  = e >> 3;          // 0..63
            int kc = e & 7;
            float4 v = *(const float4*)(W + (size_t)(bn + n) * K + k0 + kc * 4);
            Ws[kc * 4 + 0][n] = v.x;
            Ws[kc * 4 + 1][n] = v.y;
            Ws[kc * 4 + 2][n] = v.z;
            Ws[kc * 4 + 3][n] = v.w;
        }
        __syncthreads();

#pragma unroll 8
        for (int kk = 0; kk < BK; kk++) {
            float a0[4], a1[4], bb[4];
            *(float4*)a0 = *(const float4*)&As[kk][ty * 8];
            *(float4*)a1 = *(const float4*)&As[kk][ty * 8 + 4];
            *(float4*)bb = *(const float4*)&Ws[kk][tx * 4];
#pragma unroll
            for (int i = 0; i < 4; i++)
#pragma unroll
                for (int j = 0; j < 4; j++) {
                    acc[i][j]     += a0[i] * bb[j];
                    acc[i + 4][j] += a1[i] * bb[j];
                }
        }
        __syncthreads();
    }

#pragma unroll
    for (int i = 0; i < 8; i++) {
        float4 v = make_float4(acc[i][0], acc[i][1], acc[i][2], acc[i][3]);
        *(float4*)(Cout + (size_t)(bm + ty * 8 + i) * N + bn + tx * 4) = v;
    }
}

// ===========================================================================
// RoPE + layout scatter.
// raw: (B*T, heads*64) row-major -> dst: (B, heads, T, 64)
// If doRope: out[2i]   = x[2i]*cos[2i]   - x[2i+1]*sin[2i]
//            out[2i+1] = x[2i+1]*cos[2i+1] + x[2i]*sin[2i+1]
// Each thread handles one (even,odd) pair.
// ===========================================================================
__global__ void rope_scatter(const float* __restrict__ raw,
                             const float* __restrict__ cosT,
                             const float* __restrict__ sinT,
                             float* __restrict__ dst,
                             int heads, float scale, int doRope)
{
    const long long total = (long long)B_ * T_ * heads * (D_ / 2);
    long long p = (long long)blockIdx.x * blockDim.x + threadIdx.x;
    if (p >= total) return;

    const int n2 = heads * (D_ / 2);
    long long bt = p / n2;
    int r  = (int)(p % n2);
    int h  = r / (D_ / 2);
    int d  = (r % (D_ / 2)) * 2;
    int t  = (int)(bt % T_);
    int b  = (int)(bt / T_);

    const float* src = raw + bt * (size_t)(heads * D_) + h * D_ + d;
    float x1 = src[0];
    float x2 = src[1];
    float o1, o2;
    if (doRope) {
        float c1 = cosT[t * D_ + d],     s1 = sinT[t * D_ + d];
        float c2 = cosT[t * D_ + d + 1], s2 = sinT[t * D_ + d + 1];
        o1 = x1 * c1 - x2 * s1;
        o2 = x2 * c2 + x1 * s2;
    } else {
        o1 = x1; o2 = x2;
    }
    size_t oi = (((size_t)b * heads + h) * T_ + t) * D_ + d;
    dst[oi]     = o1 * scale;
    dst[oi + 1] = o2 * scale;
}

// ===========================================================================
// Causal flash attention (GQA): per block = 64 query rows of one (b,h).
// Q: g_q (B,H,T,D) pre-scaled by 1/sqrt(D). K/V: d_out regions (B,Hk,T,D).
// Output: g_o (B,T,H*D).
// ===========================================================================
#define FS 65                       // padded smem row stride
#define FLASH_SMEM (4 * 64 * FS * 4)  // Qs,Ks,Vs,Ps = 66560 bytes

__device__ __forceinline__ float rmax16(float v) {
#pragma unroll
    for (int o = 8; o > 0; o >>= 1) v = fmaxf(v, __shfl_xor_sync(0xffffffffu, v, o));
    return v;
}
__device__ __forceinline__ float rsum16(float v) {
#pragma unroll
    for (int o = 8; o > 0; o >>= 1) v += __shfl_xor_sync(0xffffffffu, v, o);
    return v;
}

__global__ __launch_bounds__(256)
void flash_kernel(const float* __restrict__ Qall,
                  const float* __restrict__ Kall,
                  const float* __restrict__ Vall,
                  float* __restrict__ Oall)
{
    extern __shared__ float sm[];
    float* Qs = sm;                 // [64][FS]
    float* Ks = sm + 64 * FS;
    float* Vs = sm + 2 * 64 * FS;
    float* Ps = sm + 3 * 64 * FS;

    const int qb  = blockIdx.x;         // 0..31 (query block)
    const int bh  = blockIdx.y;         // 0..63 = b*H + h
    const int b   = bh >> 5;
    const int h   = bh & 31;
    const int kh  = h >> 3;             // h / N_REP
    const int tid = threadIdx.x;
    const int tx  = tid & 15;
    const int ty  = tid >> 4;
    const int q0  = qb * 64;

    const float* Qp = Qall + ((size_t)bh * T_ + q0) * D_;
    const float* Kp = Kall + ((size_t)(b * HK_ + kh) * T_) * D_;
    const float* Vp = Vall + ((size_t)(b * HK_ + kh) * T_) * D_;

    // Load Q tile (64x64)
#pragma unroll
    for (int r = 0; r < 4; r++) {
        int e   = tid + r * 256;
        int row = e >> 4;
        int c4  = (e & 15) * 4;
        float4 v = *(const float4*)(Qp + (size_t)row * D_ + c4);
        Qs[row * FS + c4 + 0] = v.x;
        Qs[row * FS + c4 + 1] = v.y;
        Qs[row * FS + c4 + 2] = v.z;
        Qs[row * FS + c4 + 3] = v.w;
    }

    float m[4], l[4], o[4][4];
#pragma unroll
    for (int i = 0; i < 4; i++) {
        m[i] = -1e30f; l[i] = 0.f;
#pragma unroll
        for (int j = 0; j < 4; j++) o[i][j] = 0.f;
    }

    for (int kb = 0; kb <= qb; kb++) {
        __syncthreads();   // previous iter's Ks/Vs/Ps readers done
        // Load K,V tiles (64x64 each)
#pragma unroll
        for (int r = 0; r < 4; r++) {
            int e   = tid + r * 256;
            int row = e >> 4;
            int c4  = (e & 15) * 4;
            size_t g = ((size_t)(kb * 64 + row)) * D_ + c4;
            float4 kv = *(const float4*)(Kp + g);
            float4 vv = *(const float4*)(Vp + g);
            Ks[row * FS + c4 + 0] = kv.x; Ks[row * FS + c4 + 1] = kv.y;
            Ks[row * FS + c4 + 2] = kv.z; Ks[row * FS + c4 + 3] = kv.w;
            Vs[row * FS + c4 + 0] = vv.x; Vs[row * FS + c4 + 1] = vv.y;
            Vs[row * FS + c4 + 2] = vv.z; Vs[row * FS + c4 + 3] = vv.w;
        }
        __syncthreads();

        // S = Q K^T  (4x4 per thread; rows ty*4+i, cols tx*4+j)
        float s[4][4];
#pragma unroll
        for (int i = 0; i < 4; i++)
#pragma unroll
            for (int j = 0; j < 4; j++) s[i][j] = 0.f;

#pragma unroll 8
        for (int d = 0; d < 64; d++) {
            float qv[4], kv[4];
#pragma unroll
            for (int i = 0; i < 4; i++) qv[i] = Qs[(ty * 4 + i) * FS + d];
#pragma unroll
            for (int j = 0; j < 4; j++) kv[j] = Ks[(tx * 4 + j) * FS + d];
#pragma unroll
            for (int i = 0; i < 4; i++)
#pragma unroll
                for (int j = 0; j < 4; j++) s[i][j] += qv[i] * kv[j];
        }

        // Causal mask on the diagonal block
        if (kb == qb) {
#pragma unroll
            for (int i = 0; i < 4; i++)
#pragma unroll
                for (int j = 0; j < 4; j++)
                    if (tx * 4 + j > ty * 4 + i) s[i][j] = -1e30f;
        }

        // Online softmax per row (16 lanes of a half-warp share a row group)
#pragma unroll
        for (int i = 0; i < 4; i++) {
            float mx = fmaxf(fmaxf(s[i][0], s[i][1]), fmaxf(s[i][2], s[i][3]));
            mx = rmax16(mx);
            float mn = fmaxf(m[i], mx);
            float alpha = __expf(m[i] - mn);
            float ps = 0.f;
#pragma unroll
            for (int j = 0; j < 4; j++) {
                s[i][j] = __expf(s[i][j] - mn);
                ps += s[i][j];
            }
            ps = rsum16(ps);
            l[i] = l[i] * alpha + ps;
            m[i] = mn;
#pragma unroll
            for (int j = 0; j < 4; j++) {
                o[i][j] *= alpha;
                Ps[(ty * 4 + i) * FS + tx * 4 + j] = s[i][j];
            }
        }
        __syncthreads();

        // O += P V  (rows ty*4+i, D cols tx*4+j)
#pragma unroll 8
        for (int ss = 0; ss < 64; ss++) {
            float pv[4], vv[4];
#pragma unroll
            for (int i = 0; i < 4; i++) pv[i] = Ps[(ty * 4 + i) * FS + ss];
#pragma unroll
            for (int j = 0; j < 4; j++) vv[j] = Vs[ss * FS + tx * 4 + j];
#pragma unroll
            for (int i = 0; i < 4; i++)
#pragma unroll
                for (int j = 0; j < 4; j++) o[i][j] += pv[i] * vv[j];
        }
    }

    // Epilogue: normalize, write to (B,T,H*D)
#pragma unroll
    for (int i = 0; i < 4; i++) {
        float inv = 1.0f / l[i];
        size_t row = (size_t)b * T_ + q0 + ty * 4 + i;
        float* dst = Oall + row * (H_ * D_) + h * D_ + tx * 4;
#pragma unroll
        for (int j = 0; j < 4; j++) dst[j] = o[i][j] * inv;
    }
}

// ===========================================================================
extern "C" void kernel_launch(void* const* d_in, const int* in_sizes, int n_in,
                              void* d_out, int out_size)
{
    const float* x    = (const float*)d_in[0];
    const float* cosT = (const float*)d_in[1];
    const float* sinT = (const float*)d_in[2];
    const float* wq   = (const float*)d_in[3];
    const float* wk   = (const float*)d_in[4];
    const float* wv   = (const float*)d_in[5];
    const float* wo   = (const float*)d_in[6];

    float* out   = (float*)d_out;
    float* out_k = out   + (size_t)B_ * T_ * C_;          // k region (B,Hk,T,D)
    float* out_v = out_k + (size_t)B_ * HK_ * T_ * D_;    // v region

    float *qraw, *kraw, *vraw, *qrs, *obuf;
    cudaGetSymbolAddress((void**)&qraw, g_qraw);
    cudaGetSymbolAddress((void**)&kraw, g_kraw);
    cudaGetSymbolAddress((void**)&vraw, g_vraw);
    cudaGetSymbolAddress((void**)&qrs,  g_q);
    cudaGetSymbolAddress((void**)&obuf, g_o);

    cudaFuncSetAttribute(flash_kernel,
                         cudaFuncAttributeMaxDynamicSharedMemorySize, FLASH_SMEM);

    dim3 blk(256);

    // Projections
    gemm_nt<<<dim3((H_ * D_) / BN, MROWS / BM), blk>>>(x, wq, qraw, MROWS, H_ * D_, C_);
    gemm_nt<<<dim3((HK_ * D_) / BN, MROWS / BM), blk>>>(x, wk, kraw, MROWS, HK_ * D_, C_);
    gemm_nt<<<dim3((HK_ * D_) / BN, MROWS / BM), blk>>>(x, wv, vraw, MROWS, HK_ * D_, C_);

    // RoPE + layout (q scaled by 1/sqrt(D); k roped into d_out; v copied into d_out)
    {
        long long pq = (long long)B_ * T_ * H_ * (D_ / 2);
        long long pk = (long long)B_ * T_ * HK_ * (D_ / 2);
        rope_scatter<<<(unsigned)((pq + 255) / 256), 256>>>(qraw, cosT, sinT, qrs, H_, 0.125f, 1);
        rope_scatter<<<(unsigned)((pk + 255) / 256), 256>>>(kraw, cosT, sinT, out_k, HK_, 1.0f, 1);
        rope_scatter<<<(unsigned)((pk + 255) / 256), 256>>>(vraw, cosT, sinT, out_v, HK_, 1.0f, 0);
    }

    // Flash attention
    flash_kernel<<<dim3(T_ / 64, B_ * H_), blk, FLASH_SMEM>>>(qrs, out_k, out_v, obuf);

    // Output projection
    gemm_nt<<<dim3(C_ / BN, MROWS / BM), blk>>>(obuf, wo, out, MROWS, C_, H_ * D_);
}

// round 6
// speedup vs baseline: 1.3849x; 1.3849x over previous
#include <cuda_runtime.h>
#include <cuda_bf16.h>
#include <math.h>
#include <stdint.h>

// Problem constants
#define B_   2
#define T_   2048
#define C_   2048
#define H_   32
#define HK_  4
#define D_   64
#define MROWS (B_ * T_)          // 4096

// ---------------- scratch (static device globals; no allocation) ----------
__device__ float g_qraw[(long long)MROWS * (H_ * D_)];   // (B*T, 2048) raw q proj
__device__ float g_kraw[(long long)MROWS * (HK_ * D_)];  // (B*T, 256)
__device__ float g_vraw[(long long)MROWS * (HK_ * D_)];  // (B*T, 256)
__device__ float g_q   [(long long)B_ * H_ * T_ * D_];   // (B,H,T,D) roped+scaled
__device__ float g_o   [(long long)MROWS * (H_ * D_)];   // (B,T,H*D) attention out

// ===========================================================================
// Warp-level MMA helpers (sm_80+ legacy path; works on sm_100 non-'a')
// ===========================================================================
__device__ __forceinline__ uint32_t smem_u32(const void* p) {
    uint32_t a;
    asm("{ .reg .u64 t; cvta.to.shared.u64 t, %1; cvt.u32.u64 %0, t; }"
        : "=r"(a) : "l"(p));
    return a;
}

__device__ __forceinline__ void ldsm_x4(uint32_t* r, uint32_t addr) {
    asm volatile("ldmatrix.sync.aligned.m8n8.x4.shared.b16 {%0,%1,%2,%3}, [%4];"
        : "=r"(r[0]), "=r"(r[1]), "=r"(r[2]), "=r"(r[3]) : "r"(addr));
}

// D(16x8,f32) += A(16x16,bf16) * B(16x8,bf16)
__device__ __forceinline__ void mma16816(float* c, const uint32_t* a, const uint32_t* b) {
    asm volatile(
        "mma.sync.aligned.m16n8k16.row.col.f32.bf16.bf16.f32 "
        "{%0,%1,%2,%3}, {%4,%5,%6,%7}, {%8,%9}, {%0,%1,%2,%3};"
        : "+f"(c[0]), "+f"(c[1]), "+f"(c[2]), "+f"(c[3])
        : "r"(a[0]), "r"(a[1]), "r"(a[2]), "r"(a[3]), "r"(b[0]), "r"(b[1]));
}

// Split fp32 pair into (hi, lo) bf16x2 words. hi = rn(x), lo = rn(x - hi).
__device__ __forceinline__ void split_pair(float a, float b, uint32_t& hi, uint32_t& lo) {
    __nv_bfloat162 h = __floats2bfloat162_rn(a, b);   // .x = a (low halfword)
    float ra = a - __bfloat162float(h.x);
    float rb = b - __bfloat162float(h.y);
    __nv_bfloat162 l = __floats2bfloat162_rn(ra, rb);
    hi = *(uint32_t*)&h;
    lo = *(uint32_t*)&l;
}

// ===========================================================================
// Tensor-core GEMM:  C[M,N] = A[M,K] @ W[N,K]^T  (fp32 via bf16x3 split)
// Block 128x64, BK=32, 256 threads = 8 warps (4m x 2n), warp tile 32x32.
// smem: padded stride 40 halfwords (80B rows) -> conflict-optimal STS/LDSM.
// ===========================================================================
#define GP 40   // padded halfword stride

__global__ __launch_bounds__(256)
void gemm_mma(const float* __restrict__ A, const float* __restrict__ W,
              float* __restrict__ Cout, int M, int N, int K)
{
    __shared__ __align__(16) uint16_t sAhi[128 * GP];
    __shared__ __align__(16) uint16_t sAlo[128 * GP];
    __shared__ __align__(16) uint16_t sWhi[64 * GP];
    __shared__ __align__(16) uint16_t sWlo[64 * GP];

    const int tid  = threadIdx.x;
    const int wid  = tid >> 5;
    const int lane = tid & 31;
    const int wm   = wid & 3;         // warp m index (0..3) -> 32 rows
    const int wn   = wid >> 2;        // warp n index (0..1) -> 32 cols
    const int bm   = blockIdx.y * 128;
    const int bn   = blockIdx.x * 64;

    const uint32_t uAhi = smem_u32(sAhi);
    const uint32_t uAlo = smem_u32(sAlo);
    const uint32_t uWhi = smem_u32(sWhi);
    const uint32_t uWlo = smem_u32(sWlo);

    float acc[2][4][4];
#pragma unroll
    for (int i = 0; i < 2; i++)
#pragma unroll
        for (int j = 0; j < 4; j++)
#pragma unroll
            for (int q = 0; q < 4; q++) acc[i][j][q] = 0.f;

    // ldmatrix lane address components (precomputed)
    const int a_row_in = ((lane >> 3) & 1) * 8 + (lane & 7);   // row within 16
    const int a_koff   = (lane >> 4) * 8;                      // 0 or 8
    const int b_row_in = ((lane >> 4) & 1) * 8 + (lane & 7);
    const int b_koff   = ((lane >> 3) & 1) * 8;

    for (int k0 = 0; k0 < K; k0 += 32) {
        // ---- load + split A tile (128 x 32 fp32) : 2 rounds of 8 floats/thr
#pragma unroll
        for (int r = 0; r < 2; r++) {
            int g   = tid + r * 256;         // 0..511
            int row = g >> 2;                // 0..127
            int kg  = g & 3;                 // group of 8 floats
            const float4* p = (const float4*)(A + (size_t)(bm + row) * K + k0 + kg * 8);
            float4 f0 = p[0], f1 = p[1];
            uint4 hi, lo;
            split_pair(f0.x, f0.y, hi.x, lo.x);
            split_pair(f0.z, f0.w, hi.y, lo.y);
            split_pair(f1.x, f1.y, hi.z, lo.z);
            split_pair(f1.z, f1.w, hi.w, lo.w);
            int hw = row * GP + kg * 8;
            *(uint4*)(sAhi + hw) = hi;
            *(uint4*)(sAlo + hw) = lo;
        }
        // ---- load + split W tile (64 x 32 fp32) : 1 round of 8 floats/thr
        {
            int row = tid >> 2;              // 0..63
            int kg  = tid & 3;
            const float4* p = (const float4*)(W + (size_t)(bn + row) * K + k0 + kg * 8);
            float4 f0 = p[0], f1 = p[1];
            uint4 hi, lo;
            split_pair(f0.x, f0.y, hi.x, lo.x);
            split_pair(f0.z, f0.w, hi.y, lo.y);
            split_pair(f1.x, f1.y, hi.z, lo.z);
            split_pair(f1.z, f1.w, hi.w, lo.w);
            int hw = row * GP + kg * 8;
            *(uint4*)(sWhi + hw) = hi;
            *(uint4*)(sWlo + hw) = lo;
        }
        __syncthreads();

#pragma unroll
        for (int kk = 0; kk < 32; kk += 16) {
            uint32_t aHi[2][4], aLo[2][4], bHi[4][2], bLo[4][2];
            // A fragments: 2 m-frags of 16 rows
#pragma unroll
            for (int mf = 0; mf < 2; mf++) {
                int hw = (wm * 32 + mf * 16 + a_row_in) * GP + kk + a_koff;
                ldsm_x4(aHi[mf], uAhi + 2 * hw);
                ldsm_x4(aLo[mf], uAlo + 2 * hw);
            }
            // B fragments: 2 x4 calls cover 4 n-frags of 8 cols
#pragma unroll
            for (int p = 0; p < 2; p++) {
                int hw = (wn * 32 + p * 16 + b_row_in) * GP + kk + b_koff;
                uint32_t rh[4], rl[4];
                ldsm_x4(rh, uWhi + 2 * hw);
                ldsm_x4(rl, uWlo + 2 * hw);
                bHi[2 * p][0] = rh[0]; bHi[2 * p][1] = rh[1];
                bHi[2 * p + 1][0] = rh[2]; bHi[2 * p + 1][1] = rh[3];
                bLo[2 * p][0] = rl[0]; bLo[2 * p][1] = rl[1];
                bLo[2 * p + 1][0] = rl[2]; bLo[2 * p + 1][1] = rl[3];
            }
            // bf16x3: Ah*Bh + Ah*Bl + Al*Bh
#pragma unroll
            for (int mf = 0; mf < 2; mf++)
#pragma unroll
                for (int nf = 0; nf < 4; nf++) {
                    mma16816(acc[mf][nf], aHi[mf], bHi[nf]);
                    mma16816(acc[mf][nf], aHi[mf], bLo[nf]);
                    mma16816(acc[mf][nf], aLo[mf], bHi[nf]);
                }
        }
        __syncthreads();
    }

    // Epilogue: fragment -> global (float2 per quad position)
    const int gq = lane >> 2;        // 0..7
    const int qt = lane & 3;         // 0..3
#pragma unroll
    for (int mf = 0; mf < 2; mf++) {
#pragma unroll
        for (int nf = 0; nf < 4; nf++) {
            int row0 = bm + wm * 32 + mf * 16 + gq;
            int col  = bn + wn * 32 + nf * 8 + qt * 2;
            *(float2*)(Cout + (size_t)row0 * N + col) =
                make_float2(acc[mf][nf][0], acc[mf][nf][1]);
            *(float2*)(Cout + (size_t)(row0 + 8) * N + col) =
                make_float2(acc[mf][nf][2], acc[mf][nf][3]);
        }
    }
}

// ===========================================================================
// RoPE + layout scatter (unchanged)
// ===========================================================================
__global__ void rope_scatter(const float* __restrict__ raw,
                             const float* __restrict__ cosT,
                             const float* __restrict__ sinT,
                             float* __restrict__ dst,
                             int heads, float scale, int doRope)
{
    const long long total = (long long)B_ * T_ * heads * (D_ / 2);
    long long p = (long long)blockIdx.x * blockDim.x + threadIdx.x;
    if (p >= total) return;

    const int n2 = heads * (D_ / 2);
    long long bt = p / n2;
    int r  = (int)(p % n2);
    int h  = r / (D_ / 2);
    int d  = (r % (D_ / 2)) * 2;
    int t  = (int)(bt % T_);
    int b  = (int)(bt / T_);

    const float* src = raw + bt * (size_t)(heads * D_) + h * D_ + d;
    float x1 = src[0];
    float x2 = src[1];
    float o1, o2;
    if (doRope) {
        float c1 = cosT[t * D_ + d],     s1 = sinT[t * D_ + d];
        float c2 = cosT[t * D_ + d + 1], s2 = sinT[t * D_ + d + 1];
        o1 = x1 * c1 - x2 * s1;
        o2 = x2 * c2 + x1 * s2;
    } else {
        o1 = x1; o2 = x2;
    }
    size_t oi = (((size_t)b * heads + h) * T_ + t) * D_ + d;
    dst[oi]     = o1 * scale;
    dst[oi + 1] = o2 * scale;
}

// ===========================================================================
// Causal flash attention (GQA) — SIMT fp32 (unchanged from passing R4)
// ===========================================================================
#define FS 65
#define FLASH_SMEM (4 * 64 * FS * 4)

__device__ __forceinline__ float rmax16(float v) {
#pragma unroll
    for (int o = 8; o > 0; o >>= 1) v = fmaxf(v, __shfl_xor_sync(0xffffffffu, v, o));
    return v;
}
__device__ __forceinline__ float rsum16(float v) {
#pragma unroll
    for (int o = 8; o > 0; o >>= 1) v += __shfl_xor_sync(0xffffffffu, v, o);
    return v;
}

__global__ __launch_bounds__(256)
void flash_kernel(const float* __restrict__ Qall,
                  const float* __restrict__ Kall,
                  const float* __restrict__ Vall,
                  float* __restrict__ Oall)
{
    extern __shared__ float smf[];
    float* Qs = smf;
    float* Ks = smf + 64 * FS;
    float* Vs = smf + 2 * 64 * FS;
    float* Ps = smf + 3 * 64 * FS;

    const int qb  = blockIdx.x;
    const int bh  = blockIdx.y;
    const int b   = bh >> 5;
    const int h   = bh & 31;
    const int kh  = h >> 3;
    const int tid = threadIdx.x;
    const int tx  = tid & 15;
    const int ty  = tid >> 4;
    const int q0  = qb * 64;

    const float* Qp = Qall + ((size_t)bh * T_ + q0) * D_;
    const float* Kp = Kall + ((size_t)(b * HK_ + kh) * T_) * D_;
    const float* Vp = Vall + ((size_t)(b * HK_ + kh) * T_) * D_;

#pragma unroll
    for (int r = 0; r < 4; r++) {
        int e   = tid + r * 256;
        int row = e >> 4;
        int c4  = (e & 15) * 4;
        float4 v = *(const float4*)(Qp + (size_t)row * D_ + c4);
        Qs[row * FS + c4 + 0] = v.x;
        Qs[row * FS + c4 + 1] = v.y;
        Qs[row * FS + c4 + 2] = v.z;
        Qs[row * FS + c4 + 3] = v.w;
    }

    float m[4], l[4], o[4][4];
#pragma unroll
    for (int i = 0; i < 4; i++) {
        m[i] = -1e30f; l[i] = 0.f;
#pragma unroll
        for (int j = 0; j < 4; j++) o[i][j] = 0.f;
    }

    for (int kb = 0; kb <= qb; kb++) {
        __syncthreads();
#pragma unroll
        for (int r = 0; r < 4; r++) {
            int e   = tid + r * 256;
            int row = e >> 4;
            int c4  = (e & 15) * 4;
            size_t g = ((size_t)(kb * 64 + row)) * D_ + c4;
            float4 kv = *(const float4*)(Kp + g);
            float4 vv = *(const float4*)(Vp + g);
            Ks[row * FS + c4 + 0] = kv.x; Ks[row * FS + c4 + 1] = kv.y;
            Ks[row * FS + c4 + 2] = kv.z; Ks[row * FS + c4 + 3] = kv.w;
            Vs[row * FS + c4 + 0] = vv.x; Vs[row * FS + c4 + 1] = vv.y;
            Vs[row * FS + c4 + 2] = vv.z; Vs[row * FS + c4 + 3] = vv.w;
        }
        __syncthreads();

        float s[4][4];
#pragma unroll
        for (int i = 0; i < 4; i++)
#pragma unroll
            for (int j = 0; j < 4; j++) s[i][j] = 0.f;

#pragma unroll 8
        for (int d = 0; d < 64; d++) {
            float qv[4], kv[4];
#pragma unroll
            for (int i = 0; i < 4; i++) qv[i] = Qs[(ty * 4 + i) * FS + d];
#pragma unroll
            for (int j = 0; j < 4; j++) kv[j] = Ks[(tx * 4 + j) * FS + d];
#pragma unroll
            for (int i = 0; i < 4; i++)
#pragma unroll
                for (int j = 0; j < 4; j++) s[i][j] += qv[i] * kv[j];
        }

        if (kb == qb) {
#pragma unroll
            for (int i = 0; i < 4; i++)
#pragma unroll
                for (int j = 0; j < 4; j++)
                    if (tx * 4 + j > ty * 4 + i) s[i][j] = -1e30f;
        }

#pragma unroll
        for (int i = 0; i < 4; i++) {
            float mx = fmaxf(fmaxf(s[i][0], s[i][1]), fmaxf(s[i][2], s[i][3]));
            mx = rmax16(mx);
            float mn = fmaxf(m[i], mx);
            float alpha = __expf(m[i] - mn);
            float ps = 0.f;
#pragma unroll
            for (int j = 0; j < 4; j++) {
                s[i][j] = __expf(s[i][j] - mn);
                ps += s[i][j];
            }
            ps = rsum16(ps);
            l[i] = l[i] * alpha + ps;
            m[i] = mn;
#pragma unroll
            for (int j = 0; j < 4; j++) {
                o[i][j] *= alpha;
                Ps[(ty * 4 + i) * FS + tx * 4 + j] = s[i][j];
            }
        }
        __syncthreads();

#pragma unroll 8
        for (int ss = 0; ss < 64; ss++) {
            float pv[4], vv[4];
#pragma unroll
            for (int i = 0; i < 4; i++) pv[i] = Ps[(ty * 4 + i) * FS + ss];
#pragma unroll
            for (int j = 0; j < 4; j++) vv[j] = Vs[ss * FS + tx * 4 + j];
#pragma unroll
            for (int i = 0; i < 4; i++)
#pragma unroll
                for (int j = 0; j < 4; j++) o[i][j] += pv[i] * vv[j];
        }
    }

#pragma unroll
    for (int i = 0; i < 4; i++) {
        float inv = 1.0f / l[i];
        size_t row = (size_t)b * T_ + q0 + ty * 4 + i;
        float* dst = Oall + row * (H_ * D_) + h * D_ + tx * 4;
#pragma unroll
        for (int j = 0; j < 4; j++) dst[j] = o[i][j] * inv;
    }
}

// ===========================================================================
extern "C" void kernel_launch(void* const* d_in, const int* in_sizes, int n_in,
                              void* d_out, int out_size)
{
    const float* x    = (const float*)d_in[0];
    const float* cosT = (const float*)d_in[1];
    const float* sinT = (const float*)d_in[2];
    const float* wq   = (const float*)d_in[3];
    const float* wk   = (const float*)d_in[4];
    const float* wv   = (const float*)d_in[5];
    const float* wo   = (const float*)d_in[6];

    float* out   = (float*)d_out;
    float* out_k = out   + (size_t)B_ * T_ * C_;
    float* out_v = out_k + (size_t)B_ * HK_ * T_ * D_;

    float *qraw, *kraw, *vraw, *qrs, *obuf;
    cudaGetSymbolAddress((void**)&qraw, g_qraw);
    cudaGetSymbolAddress((void**)&kraw, g_kraw);
    cudaGetSymbolAddress((void**)&vraw, g_vraw);
    cudaGetSymbolAddress((void**)&qrs,  g_q);
    cudaGetSymbolAddress((void**)&obuf, g_o);

    cudaFuncSetAttribute(flash_kernel,
                         cudaFuncAttributeMaxDynamicSharedMemorySize, FLASH_SMEM);

    dim3 blk(256);

    // Projections (tensor-core bf16x3)
    gemm_mma<<<dim3((H_ * D_) / 64, MROWS / 128), blk>>>(x, wq, qraw, MROWS, H_ * D_, C_);
    gemm_mma<<<dim3((HK_ * D_) / 64, MROWS / 128), blk>>>(x, wk, kraw, MROWS, HK_ * D_, C_);
    gemm_mma<<<dim3((HK_ * D_) / 64, MROWS / 128), blk>>>(x, wv, vraw, MROWS, HK_ * D_, C_);

    // RoPE + layout
    {
        long long pq = (long long)B_ * T_ * H_ * (D_ / 2);
        long long pk = (long long)B_ * T_ * HK_ * (D_ / 2);
        rope_scatter<<<(unsigned)((pq + 255) / 256), 256>>>(qraw, cosT, sinT, qrs, H_, 0.125f, 1);
        rope_scatter<<<(unsigned)((pk + 255) / 256), 256>>>(kraw, cosT, sinT, out_k, HK_, 1.0f, 1);
        rope_scatter<<<(unsigned)((pk + 255) / 256), 256>>>(vraw, cosT, sinT, out_v, HK_, 1.0f, 0);
    }

    // Flash attention (SIMT fp32)
    flash_kernel<<<dim3(T_ / 64, B_ * H_), blk, FLASH_SMEM>>>(qrs, out_k, out_v, obuf);

    // Output projection (tensor-core bf16x3)
    gemm_mma<<<dim3(C_ / 64, MROWS / 128), blk>>>(obuf, wo, out, MROWS, C_, H_ * D_);
}

// round 7
// speedup vs baseline: 1.9780x; 1.4283x over previous
#include <cuda_runtime.h>
#include <cuda_bf16.h>
#include <math.h>
#include <stdint.h>

// Problem constants
#define B_   2
#define T_   2048
#define C_   2048
#define H_   32
#define HK_  4
#define D_   64
#define MROWS (B_ * T_)          // 4096

// ---------------- scratch (static device globals; no allocation) ----------
__device__ float g_qraw[(long long)MROWS * (H_ * D_)];   // (B*T, 2048) raw q proj
__device__ float g_kraw[(long long)MROWS * (HK_ * D_)];  // (B*T, 256)
__device__ float g_vraw[(long long)MROWS * (HK_ * D_)];  // (B*T, 256)
__device__ float g_q   [(long long)B_ * H_ * T_ * D_];   // (B,H,T,D) roped+scaled
__device__ float g_o   [(long long)MROWS * (H_ * D_)];   // (B,T,H*D) attention out

// ===========================================================================
// Warp-level MMA helpers (sm_80+ legacy path; works on sm_100 non-'a')
// ===========================================================================
__device__ __forceinline__ uint32_t smem_u32(const void* p) {
    uint32_t a;
    asm("{ .reg .u64 t; cvta.to.shared.u64 t, %1; cvt.u32.u64 %0, t; }"
        : "=r"(a) : "l"(p));
    return a;
}

__device__ __forceinline__ void ldsm_x4(uint32_t* r, uint32_t addr) {
    asm volatile("ldmatrix.sync.aligned.m8n8.x4.shared.b16 {%0,%1,%2,%3}, [%4];"
        : "=r"(r[0]), "=r"(r[1]), "=r"(r[2]), "=r"(r[3]) : "r"(addr));
}

// D(16x8,f32) += A(16x16,bf16) * B(16x8,bf16)
__device__ __forceinline__ void mma16816(float* c, const uint32_t* a, const uint32_t* b) {
    asm volatile(
        "mma.sync.aligned.m16n8k16.row.col.f32.bf16.bf16.f32 "
        "{%0,%1,%2,%3}, {%4,%5,%6,%7}, {%8,%9}, {%0,%1,%2,%3};"
        : "+f"(c[0]), "+f"(c[1]), "+f"(c[2]), "+f"(c[3])
        : "r"(a[0]), "r"(a[1]), "r"(a[2]), "r"(a[3]), "r"(b[0]), "r"(b[1]));
}

// Split fp32 pair into (hi, lo) bf16x2 words. hi = rn(x), lo = rn(x - hi).
__device__ __forceinline__ void split_pair(float a, float b, uint32_t& hi, uint32_t& lo) {
    __nv_bfloat162 h = __floats2bfloat162_rn(a, b);   // .x = a (low halfword)
    float ra = a - __bfloat162float(h.x);
    float rb = b - __bfloat162float(h.y);
    __nv_bfloat162 l = __floats2bfloat162_rn(ra, rb);
    hi = *(uint32_t*)&h;
    lo = *(uint32_t*)&l;
}

// ===========================================================================
// Tensor-core GEMM:  C[M,N] = A[M,K] @ W[N,K]^T  (fp32 via bf16x3 split)
// Block 128x64, BK=32, 256 threads = 8 warps (4m x 2n), warp tile 32x32.
// ===========================================================================
#define GP 40   // padded halfword stride

__global__ __launch_bounds__(256)
void gemm_mma(const float* __restrict__ A, const float* __restrict__ W,
              float* __restrict__ Cout, int M, int N, int K)
{
    __shared__ __align__(16) uint16_t sAhi[128 * GP];
    __shared__ __align__(16) uint16_t sAlo[128 * GP];
    __shared__ __align__(16) uint16_t sWhi[64 * GP];
    __shared__ __align__(16) uint16_t sWlo[64 * GP];

    const int tid  = threadIdx.x;
    const int wid  = tid >> 5;
    const int lane = tid & 31;
    const int wm   = wid & 3;
    const int wn   = wid >> 2;
    const int bm   = blockIdx.y * 128;
    const int bn   = blockIdx.x * 64;

    const uint32_t uAhi = smem_u32(sAhi);
    const uint32_t uAlo = smem_u32(sAlo);
    const uint32_t uWhi = smem_u32(sWhi);
    const uint32_t uWlo = smem_u32(sWlo);

    float acc[2][4][4];
#pragma unroll
    for (int i = 0; i < 2; i++)
#pragma unroll
        for (int j = 0; j < 4; j++)
#pragma unroll
            for (int q = 0; q < 4; q++) acc[i][j][q] = 0.f;

    const int a_row_in = ((lane >> 3) & 1) * 8 + (lane & 7);
    const int a_koff   = (lane >> 4) * 8;
    const int b_row_in = ((lane >> 4) & 1) * 8 + (lane & 7);
    const int b_koff   = ((lane >> 3) & 1) * 8;

    for (int k0 = 0; k0 < K; k0 += 32) {
#pragma unroll
        for (int r = 0; r < 2; r++) {
            int g   = tid + r * 256;
            int row = g >> 2;
            int kg  = g & 3;
            const float4* p = (const float4*)(A + (size_t)(bm + row) * K + k0 + kg * 8);
            float4 f0 = p[0], f1 = p[1];
            uint4 hi, lo;
            split_pair(f0.x, f0.y, hi.x, lo.x);
            split_pair(f0.z, f0.w, hi.y, lo.y);
            split_pair(f1.x, f1.y, hi.z, lo.z);
            split_pair(f1.z, f1.w, hi.w, lo.w);
            int hw = row * GP + kg * 8;
            *(uint4*)(sAhi + hw) = hi;
            *(uint4*)(sAlo + hw) = lo;
        }
        {
            int row = tid >> 2;
            int kg  = tid & 3;
            const float4* p = (const float4*)(W + (size_t)(bn + row) * K + k0 + kg * 8);
            float4 f0 = p[0], f1 = p[1];
            uint4 hi, lo;
            split_pair(f0.x, f0.y, hi.x, lo.x);
            split_pair(f0.z, f0.w, hi.y, lo.y);
            split_pair(f1.x, f1.y, hi.z, lo.z);
            split_pair(f1.z, f1.w, hi.w, lo.w);
            int hw = row * GP + kg * 8;
            *(uint4*)(sWhi + hw) = hi;
            *(uint4*)(sWlo + hw) = lo;
        }
        __syncthreads();

#pragma unroll
        for (int kk = 0; kk < 32; kk += 16) {
            uint32_t aHi[2][4], aLo[2][4], bHi[4][2], bLo[4][2];
#pragma unroll
            for (int mf = 0; mf < 2; mf++) {
                int hw = (wm * 32 + mf * 16 + a_row_in) * GP + kk + a_koff;
                ldsm_x4(aHi[mf], uAhi + 2 * hw);
                ldsm_x4(aLo[mf], uAlo + 2 * hw);
            }
#pragma unroll
            for (int p = 0; p < 2; p++) {
                int hw = (wn * 32 + p * 16 + b_row_in) * GP + kk + b_koff;
                uint32_t rh[4], rl[4];
                ldsm_x4(rh, uWhi + 2 * hw);
                ldsm_x4(rl, uWlo + 2 * hw);
                bHi[2 * p][0] = rh[0]; bHi[2 * p][1] = rh[1];
                bHi[2 * p + 1][0] = rh[2]; bHi[2 * p + 1][1] = rh[3];
                bLo[2 * p][0] = rl[0]; bLo[2 * p][1] = rl[1];
                bLo[2 * p + 1][0] = rl[2]; bLo[2 * p + 1][1] = rl[3];
            }
#pragma unroll
            for (int mf = 0; mf < 2; mf++)
#pragma unroll
                for (int nf = 0; nf < 4; nf++) {
                    mma16816(acc[mf][nf], aHi[mf], bHi[nf]);
                    mma16816(acc[mf][nf], aHi[mf], bLo[nf]);
                    mma16816(acc[mf][nf], aLo[mf], bHi[nf]);
                }
        }
        __syncthreads();
    }

    const int gq = lane >> 2;
    const int qt = lane & 3;
#pragma unroll
    for (int mf = 0; mf < 2; mf++) {
#pragma unroll
        for (int nf = 0; nf < 4; nf++) {
            int row0 = bm + wm * 32 + mf * 16 + gq;
            int col  = bn + wn * 32 + nf * 8 + qt * 2;
            *(float2*)(Cout + (size_t)row0 * N + col) =
                make_float2(acc[mf][nf][0], acc[mf][nf][1]);
            *(float2*)(Cout + (size_t)(row0 + 8) * N + col) =
                make_float2(acc[mf][nf][2], acc[mf][nf][3]);
        }
    }
}

// ===========================================================================
// RoPE + layout scatter (unchanged)
// ===========================================================================
__global__ void rope_scatter(const float* __restrict__ raw,
                             const float* __restrict__ cosT,
                             const float* __restrict__ sinT,
                             float* __restrict__ dst,
                             int heads, float scale, int doRope)
{
    const long long total = (long long)B_ * T_ * heads * (D_ / 2);
    long long p = (long long)blockIdx.x * blockDim.x + threadIdx.x;
    if (p >= total) return;

    const int n2 = heads * (D_ / 2);
    long long bt = p / n2;
    int r  = (int)(p % n2);
    int h  = r / (D_ / 2);
    int d  = (r % (D_ / 2)) * 2;
    int t  = (int)(bt % T_);
    int b  = (int)(bt / T_);

    const float* src = raw + bt * (size_t)(heads * D_) + h * D_ + d;
    float x1 = src[0];
    float x2 = src[1];
    float o1, o2;
    if (doRope) {
        float c1 = cosT[t * D_ + d],     s1 = sinT[t * D_ + d];
        float c2 = cosT[t * D_ + d + 1], s2 = sinT[t * D_ + d + 1];
        o1 = x1 * c1 - x2 * s1;
        o2 = x2 * c2 + x1 * s2;
    } else {
        o1 = x1; o2 = x2;
    }
    size_t oi = (((size_t)b * heads + h) * T_ + t) * D_ + d;
    dst[oi]     = o1 * scale;
    dst[oi + 1] = o2 * scale;
}

// ===========================================================================
// Tensor-core causal flash attention (GQA), bf16x3 split precision.
// Block = 64 q rows of one (b,h); 128 threads = 4 warps x 16 q rows.
// Q fragments live in registers across the whole KV loop.
// K smem [s][d]; V smem transposed [d][s]; both hi/lo bf16, stride 72 hw.
// ===========================================================================
#define FP 72                 // padded halfword stride (conflict-free ldsm)
#define FK_HI 0
#define FK_LO 4608
#define FV_HI 9216
#define FV_LO 13824
// Q phase reuses same buffer: Qhi at 0, Qlo at 4608 (64*72 = 4608 hw each)

__global__ __launch_bounds__(128)
void flash_mma(const float* __restrict__ Qall,
               const float* __restrict__ Kall,
               const float* __restrict__ Vall,
               float* __restrict__ Oall)
{
    __shared__ __align__(16) uint16_t buf[18432];   // 36,864 bytes

    const int qb  = blockIdx.x;          // 0..31
    const int bh  = blockIdx.y;          // b*H + h
    const int b   = bh >> 5;
    const int h   = bh & 31;
    const int kh  = h >> 3;
    const int tid = threadIdx.x;
    const int wm  = tid >> 5;            // warp id: rows [16wm, 16wm+16)
    const int lane = tid & 31;
    const int gq  = lane >> 2;
    const int qt  = lane & 3;
    const int q0  = qb * 64;

    const float* Qp = Qall + ((size_t)bh * T_ + q0) * D_;
    const float* Kp = Kall + ((size_t)(b * HK_ + kh) * T_) * D_;
    const float* Vp = Vall + ((size_t)(b * HK_ + kh) * T_) * D_;

    const uint32_t sbase = smem_u32(buf);

    // ---- Load Q (64x64) into smem hi/lo (row per 2 threads, 32 d each) ----
    {
        int row  = tid >> 1;
        int half = tid & 1;
        const float* src = Qp + (size_t)row * D_ + 32 * half;
#pragma unroll
        for (int g = 0; g < 4; g++) {
            float4 f0 = *(const float4*)(src + 8 * g);
            float4 f1 = *(const float4*)(src + 8 * g + 4);
            uint4 hi, lo;
            split_pair(f0.x, f0.y, hi.x, lo.x);
            split_pair(f0.z, f0.w, hi.y, lo.y);
            split_pair(f1.x, f1.y, hi.z, lo.z);
            split_pair(f1.z, f1.w, hi.w, lo.w);
            int hw = row * FP + 32 * half + 8 * g;
            *(uint4*)&buf[hw]        = hi;
            *(uint4*)&buf[4608 + hw] = lo;
        }
    }
    __syncthreads();

    const int a_row = ((lane >> 3) & 1) * 8 + (lane & 7);
    const int a_k   = (lane >> 4) * 8;
    const int b_row = ((lane >> 4) & 1) * 8 + (lane & 7);
    const int b_k   = ((lane >> 3) & 1) * 8;

    // Q A-fragments in registers (4 k-chunks of d)
    uint32_t qhi[4][4], qlo[4][4];
#pragma unroll
    for (int dk = 0; dk < 4; dk++) {
        int hw = (wm * 16 + a_row) * FP + dk * 16 + a_k;
        ldsm_x4(qhi[dk], sbase + 2 * (0 + hw));
        ldsm_x4(qlo[dk], sbase + 2 * (4608 + hw));
    }
    __syncthreads();   // Q reads done; buffer now reusable for K/V

    float m0 = -1e30f, m1 = -1e30f, l0 = 0.f, l1 = 0.f;
    float o[8][4];
#pragma unroll
    for (int nf = 0; nf < 8; nf++)
#pragma unroll
        for (int q = 0; q < 4; q++) o[nf][q] = 0.f;

    for (int kb = 0; kb <= qb; kb++) {
        // ---- Load K tile [64 s][64 d] hi/lo ----
        {
            int row  = tid >> 1;
            int half = tid & 1;
            const float* src = Kp + (size_t)(kb * 64 + row) * D_ + 32 * half;
#pragma unroll
            for (int g = 0; g < 4; g++) {
                float4 f0 = *(const float4*)(src + 8 * g);
                float4 f1 = *(const float4*)(src + 8 * g + 4);
                uint4 hi, lo;
                split_pair(f0.x, f0.y, hi.x, lo.x);
                split_pair(f0.z, f0.w, hi.y, lo.y);
                split_pair(f1.x, f1.y, hi.z, lo.z);
                split_pair(f1.z, f1.w, hi.w, lo.w);
                int hw = row * FP + 32 * half + 8 * g;
                *(uint4*)&buf[FK_HI + hw] = hi;
                *(uint4*)&buf[FK_LO + hw] = lo;
            }
        }
        // ---- Load V tile transposed [64 d][64 s] hi/lo ----
#pragma unroll
        for (int u2 = 0; u2 < 2; u2++) {
            int u  = tid + u2 * 128;
            int s0 = 2 * (u & 31);
            int d0 = 8 * (u >> 5);
            const float* r0p = Vp + (size_t)(kb * 64 + s0) * D_ + d0;
            const float* r1p = r0p + D_;
            float4 a0 = *(const float4*)(r0p), a1 = *(const float4*)(r0p + 4);
            float4 c0 = *(const float4*)(r1p), c1 = *(const float4*)(r1p + 4);
            float r0v[8] = {a0.x, a0.y, a0.z, a0.w, a1.x, a1.y, a1.z, a1.w};
            float r1v[8] = {c0.x, c0.y, c0.z, c0.w, c1.x, c1.y, c1.z, c1.w};
#pragma unroll
            for (int i = 0; i < 8; i++) {
                uint32_t hi, lo;
                split_pair(r0v[i], r1v[i], hi, lo);   // low hw = s0, high = s0+1
                int hw = (d0 + i) * FP + s0;
                *(uint32_t*)&buf[FV_HI + hw] = hi;
                *(uint32_t*)&buf[FV_LO + hw] = lo;
            }
        }
        __syncthreads();

        // ---- S = Q K^T (3-way split), n-frags: 8 x 8 keys ----
        float s[8][4];
#pragma unroll
        for (int nf = 0; nf < 8; nf++)
#pragma unroll
            for (int q = 0; q < 4; q++) s[nf][q] = 0.f;

#pragma unroll
        for (int dk = 0; dk < 4; dk++) {
            uint32_t kfh[4][4], kfl[4][4];
#pragma unroll
            for (int g = 0; g < 4; g++) {
                int hw = (16 * g + b_row) * FP + dk * 16 + b_k;
                ldsm_x4(kfh[g], sbase + 2 * (FK_HI + hw));
                ldsm_x4(kfl[g], sbase + 2 * (FK_LO + hw));
            }
#pragma unroll
            for (int g = 0; g < 4; g++) {
                mma16816(s[2 * g],     qhi[dk], &kfh[g][0]);
                mma16816(s[2 * g],     qhi[dk], &kfl[g][0]);
                mma16816(s[2 * g],     qlo[dk], &kfh[g][0]);
                mma16816(s[2 * g + 1], qhi[dk], &kfh[g][2]);
                mma16816(s[2 * g + 1], qhi[dk], &kfl[g][2]);
                mma16816(s[2 * g + 1], qlo[dk], &kfh[g][2]);
            }
        }

        // ---- causal mask on diagonal block ----
        if (kb == qb) {
            int r0g = 16 * wm + gq;
            int r1g = r0g + 8;
#pragma unroll
            for (int nf = 0; nf < 8; nf++) {
                int c = nf * 8 + 2 * qt;
                if (c     > r0g) s[nf][0] = -1e30f;
                if (c + 1 > r0g) s[nf][1] = -1e30f;
                if (c     > r1g) s[nf][2] = -1e30f;
                if (c + 1 > r1g) s[nf][3] = -1e30f;
            }
        }

        // ---- online softmax (rows gq and gq+8; quad = 4 lanes/row) ----
        float mx0 = -1e30f, mx1 = -1e30f;
#pragma unroll
        for (int nf = 0; nf < 8; nf++) {
            mx0 = fmaxf(mx0, fmaxf(s[nf][0], s[nf][1]));
            mx1 = fmaxf(mx1, fmaxf(s[nf][2], s[nf][3]));
        }
        mx0 = fmaxf(mx0, __shfl_xor_sync(0xffffffffu, mx0, 1));
        mx0 = fmaxf(mx0, __shfl_xor_sync(0xffffffffu, mx0, 2));
        mx1 = fmaxf(mx1, __shfl_xor_sync(0xffffffffu, mx1, 1));
        mx1 = fmaxf(mx1, __shfl_xor_sync(0xffffffffu, mx1, 2));
        float mn0 = fmaxf(m0, mx0), mn1 = fmaxf(m1, mx1);
        float al0 = __expf(m0 - mn0), al1 = __expf(m1 - mn1);
        float sum0 = 0.f, sum1 = 0.f;
#pragma unroll
        for (int nf = 0; nf < 8; nf++) {
            s[nf][0] = __expf(s[nf][0] - mn0);
            s[nf][1] = __expf(s[nf][1] - mn0);
            s[nf][2] = __expf(s[nf][2] - mn1);
            s[nf][3] = __expf(s[nf][3] - mn1);
            sum0 += s[nf][0] + s[nf][1];
            sum1 += s[nf][2] + s[nf][3];
        }
        sum0 += __shfl_xor_sync(0xffffffffu, sum0, 1);
        sum0 += __shfl_xor_sync(0xffffffffu, sum0, 2);
        sum1 += __shfl_xor_sync(0xffffffffu, sum1, 1);
        sum1 += __shfl_xor_sync(0xffffffffu, sum1, 2);
        l0 = l0 * al0 + sum0;  m0 = mn0;
        l1 = l1 * al1 + sum1;  m1 = mn1;
#pragma unroll
        for (int nf = 0; nf < 8; nf++) {
            o[nf][0] *= al0; o[nf][1] *= al0;
            o[nf][2] *= al1; o[nf][3] *= al1;
        }

        // ---- pack P into A-operand fragments (hi/lo) ----
        uint32_t phi[4][4], plo[4][4];
#pragma unroll
        for (int kc = 0; kc < 4; kc++) {
            split_pair(s[2 * kc][0],     s[2 * kc][1],     phi[kc][0], plo[kc][0]);
            split_pair(s[2 * kc][2],     s[2 * kc][3],     phi[kc][1], plo[kc][1]);
            split_pair(s[2 * kc + 1][0], s[2 * kc + 1][1], phi[kc][2], plo[kc][2]);
            split_pair(s[2 * kc + 1][2], s[2 * kc + 1][3], phi[kc][3], plo[kc][3]);
        }

        // ---- O += P V (3-way split) ----
#pragma unroll
        for (int kc = 0; kc < 4; kc++) {
            uint32_t vfh[4][4], vfl[4][4];
#pragma unroll
            for (int g = 0; g < 4; g++) {
                int hw = (16 * g + b_row) * FP + kc * 16 + b_k;
                ldsm_x4(vfh[g], sbase + 2 * (FV_HI + hw));
                ldsm_x4(vfl[g], sbase + 2 * (FV_LO + hw));
            }
#pragma unroll
            for (int g = 0; g < 4; g++) {
                mma16816(o[2 * g],     phi[kc], &vfh[g][0]);
                mma16816(o[2 * g],     phi[kc], &vfl[g][0]);
                mma16816(o[2 * g],     plo[kc], &vfh[g][0]);
                mma16816(o[2 * g + 1], phi[kc], &vfh[g][2]);
                mma16816(o[2 * g + 1], phi[kc], &vfl[g][2]);
                mma16816(o[2 * g + 1], plo[kc], &vfh[g][2]);
            }
        }
        __syncthreads();   // protect K/V buffer before next iteration's stores
    }

    // ---- epilogue: normalize + write (B,T,H*D) ----
    float inv0 = 1.0f / l0, inv1 = 1.0f / l1;
    int row0 = q0 + wm * 16 + gq;
    float* dst0 = Oall + ((size_t)b * T_ + row0) * (H_ * D_) + h * D_;
    float* dst1 = dst0 + (size_t)8 * (H_ * D_);
#pragma unroll
    for (int nf = 0; nf < 8; nf++) {
        int c = nf * 8 + 2 * qt;
        *(float2*)(dst0 + c) = make_float2(o[nf][0] * inv0, o[nf][1] * inv0);
        *(float2*)(dst1 + c) = make_float2(o[nf][2] * inv1, o[nf][3] * inv1);
    }
}

// ===========================================================================
extern "C" void kernel_launch(void* const* d_in, const int* in_sizes, int n_in,
                              void* d_out, int out_size)
{
    const float* x    = (const float*)d_in[0];
    const float* cosT = (const float*)d_in[1];
    const float* sinT = (const float*)d_in[2];
    const float* wq   = (const float*)d_in[3];
    const float* wk   = (const float*)d_in[4];
    const float* wv   = (const float*)d_in[5];
    const float* wo   = (const float*)d_in[6];

    float* out   = (float*)d_out;
    float* out_k = out   + (size_t)B_ * T_ * C_;
    float* out_v = out_k + (size_t)B_ * HK_ * T_ * D_;

    float *qraw, *kraw, *vraw, *qrs, *obuf;
    cudaGetSymbolAddress((void**)&qraw, g_qraw);
    cudaGetSymbolAddress((void**)&kraw, g_kraw);
    cudaGetSymbolAddress((void**)&vraw, g_vraw);
    cudaGetSymbolAddress((void**)&qrs,  g_q);
    cudaGetSymbolAddress((void**)&obuf, g_o);

    dim3 blk(256);

    // Projections (tensor-core bf16x3)
    gemm_mma<<<dim3((H_ * D_) / 64, MROWS / 128), blk>>>(x, wq, qraw, MROWS, H_ * D_, C_);
    gemm_mma<<<dim3((HK_ * D_) / 64, MROWS / 128), blk>>>(x, wk, kraw, MROWS, HK_ * D_, C_);
    gemm_mma<<<dim3((HK_ * D_) / 64, MROWS / 128), blk>>>(x, wv, vraw, MROWS, HK_ * D_, C_);

    // RoPE + layout (q scaled by 1/sqrt(D); k roped into d_out; v copied)
    {
        long long pq = (long long)B_ * T_ * H_ * (D_ / 2);
        long long pk = (long long)B_ * T_ * HK_ * (D_ / 2);
        rope_scatter<<<(unsigned)((pq + 255) / 256), 256>>>(qraw, cosT, sinT, qrs, H_, 0.125f, 1);
        rope_scatter<<<(unsigned)((pk + 255) / 256), 256>>>(kraw, cosT, sinT, out_k, HK_, 1.0f, 1);
        rope_scatter<<<(unsigned)((pk + 255) / 256), 256>>>(vraw, cosT, sinT, out_v, HK_, 1.0f, 0);
    }

    // Flash attention (tensor-core bf16x3)
    flash_mma<<<dim3(T_ / 64, B_ * H_), 128>>>(qrs, out_k, out_v, obuf);

    // Output projection (tensor-core bf16x3)
    gemm_mma<<<dim3(C_ / 64, MROWS / 128), blk>>>(obuf, wo, out, MROWS, C_, H_ * D_);
}

// round 8
// speedup vs baseline: 2.4866x; 1.2571x over previous
#include <cuda_runtime.h>
#include <cuda_bf16.h>
#include <math.h>
#include <stdint.h>

// Problem constants
#define B_   2
#define T_   2048
#define C_   2048
#define H_   32
#define HK_  4
#define D_   64
#define MROWS (B_ * T_)          // 4096

// ---------------- scratch (static device globals; no allocation) ----------
__device__ float g_qraw[(long long)MROWS * (H_ * D_)];   // raw q proj fp32
__device__ float g_kraw[(long long)MROWS * (HK_ * D_)];
__device__ float g_vraw[(long long)MROWS * (HK_ * D_)];
__device__ float g_o   [(long long)MROWS * (H_ * D_)];   // attention out fp32

// pre-split bf16 hi/lo buffers
__device__ __nv_bfloat16 g_xh[(long long)MROWS * C_],  g_xl[(long long)MROWS * C_];
__device__ __nv_bfloat16 g_oh[(long long)MROWS * C_],  g_ol[(long long)MROWS * C_];
__device__ __nv_bfloat16 g_wqh[(long long)(H_*D_) * C_],  g_wql[(long long)(H_*D_) * C_];
__device__ __nv_bfloat16 g_wkh[(long long)(HK_*D_) * C_], g_wkl[(long long)(HK_*D_) * C_];
__device__ __nv_bfloat16 g_wvh[(long long)(HK_*D_) * C_], g_wvl[(long long)(HK_*D_) * C_];
__device__ __nv_bfloat16 g_woh[(long long)C_ * (H_*D_)],  g_wol[(long long)C_ * (H_*D_)];
__device__ __nv_bfloat16 g_qh[(long long)B_*H_*T_*D_],  g_ql[(long long)B_*H_*T_*D_];
__device__ __nv_bfloat16 g_kh[(long long)B_*HK_*T_*D_], g_kl[(long long)B_*HK_*T_*D_];
__device__ __nv_bfloat16 g_vh[(long long)B_*HK_*T_*D_], g_vl[(long long)B_*HK_*T_*D_];

// ===========================================================================
// helpers
// ===========================================================================
__device__ __forceinline__ uint32_t smem_u32(const void* p) {
    uint32_t a;
    asm("{ .reg .u64 t; cvta.to.shared.u64 t, %1; cvt.u32.u64 %0, t; }"
        : "=r"(a) : "l"(p));
    return a;
}
__device__ __forceinline__ void ldsm_x4(uint32_t* r, uint32_t addr) {
    asm volatile("ldmatrix.sync.aligned.m8n8.x4.shared.b16 {%0,%1,%2,%3}, [%4];"
        : "=r"(r[0]), "=r"(r[1]), "=r"(r[2]), "=r"(r[3]) : "r"(addr));
}
__device__ __forceinline__ void mma16816(float* c, const uint32_t* a, const uint32_t* b) {
    asm volatile(
        "mma.sync.aligned.m16n8k16.row.col.f32.bf16.bf16.f32 "
        "{%0,%1,%2,%3}, {%4,%5,%6,%7}, {%8,%9}, {%0,%1,%2,%3};"
        : "+f"(c[0]), "+f"(c[1]), "+f"(c[2]), "+f"(c[3])
        : "r"(a[0]), "r"(a[1]), "r"(a[2]), "r"(a[3]), "r"(b[0]), "r"(b[1]));
}
__device__ __forceinline__ void split_pair(float a, float b, uint32_t& hi, uint32_t& lo) {
    __nv_bfloat162 h = __floats2bfloat162_rn(a, b);
    float ra = a - __bfloat162float(h.x);
    float rb = b - __bfloat162float(h.y);
    __nv_bfloat162 l = __floats2bfloat162_rn(ra, rb);
    hi = *(uint32_t*)&h;
    lo = *(uint32_t*)&l;
}
__device__ __forceinline__ void cp_async16(uint32_t dst, const void* src) {
    asm volatile("cp.async.cg.shared.global [%0], [%1], 16;" :: "r"(dst), "l"(src));
}
#define CP_COMMIT() asm volatile("cp.async.commit_group;" ::: "memory")
#define CP_WAIT1()  asm volatile("cp.async.wait_group 1;" ::: "memory")
#define CP_WAIT0()  asm volatile("cp.async.wait_group 0;" ::: "memory")

// ===========================================================================
// fp32 -> bf16 hi/lo global split (8 floats per thread)
// ===========================================================================
__global__ void split_f32(const float* __restrict__ src,
                          __nv_bfloat16* __restrict__ hi,
                          __nv_bfloat16* __restrict__ lo, int n8)
{
    int i = blockIdx.x * blockDim.x + threadIdx.x;
    if (i >= n8) return;
    const float4* p = (const float4*)src + 2 * (size_t)i;
    float4 f0 = p[0], f1 = p[1];
    uint4 h, l;
    split_pair(f0.x, f0.y, h.x, l.x);
    split_pair(f0.z, f0.w, h.y, l.y);
    split_pair(f1.x, f1.y, h.z, l.z);
    split_pair(f1.z, f1.w, h.w, l.w);
    ((uint4*)hi)[i] = h;
    ((uint4*)lo)[i] = l;
}

// ===========================================================================
// Tensor-core GEMM on pre-split operands:
//   C[M,N](f32) = (Ah+Al)[M,K] @ (Wh+Wl)[N,K]^T   (3-term bf16 split)
// Block 128x64, BK=32, 256 threads (8 warps 4x2), cp.async 2-stage pipeline.
// ===========================================================================
#define GP 40                    // padded halfword stride
#define ST_AHI 0
#define ST_ALO (128 * GP)        // 5120
#define ST_WHI (2 * 128 * GP)    // 10240
#define ST_WLO (ST_WHI + 64 * GP)
#define STAGE_HW (ST_WLO + 64 * GP)     // 15360 hw = 30720 B
#define GEMM2_SMEM (2 * STAGE_HW * 2)   // 61440 B

__global__ __launch_bounds__(256)
void gemm_split(const __nv_bfloat16* __restrict__ Ahi, const __nv_bfloat16* __restrict__ Alo,
                const __nv_bfloat16* __restrict__ Whi, const __nv_bfloat16* __restrict__ Wlo,
                float* __restrict__ Cout, int M, int N, int K)
{
    extern __shared__ __align__(16) uint16_t smem[];
    const uint32_t sbase = smem_u32(smem);

    const int tid  = threadIdx.x;
    const int wid  = tid >> 5;
    const int lane = tid & 31;
    const int wm   = wid & 3;
    const int wn   = wid >> 2;
    const int bm   = blockIdx.y * 128;
    const int bn   = blockIdx.x * 64;

    // cp.async indices
    const int ar0 = tid >> 2;          // A row (round 0)
    const int ar1 = (tid + 256) >> 2;  // A row (round 1)
    const int akc = tid & 3;           // 16B chunk in k
    const int wr  = tid >> 2;          // W row
    const int nch = K / 32;

    float acc[2][4][4];
#pragma unroll
    for (int i = 0; i < 2; i++)
#pragma unroll
        for (int j = 0; j < 4; j++)
#pragma unroll
            for (int q = 0; q < 4; q++) acc[i][j][q] = 0.f;

    const int a_row_in = ((lane >> 3) & 1) * 8 + (lane & 7);
    const int a_koff   = (lane >> 4) * 8;
    const int b_row_in = ((lane >> 4) & 1) * 8 + (lane & 7);
    const int b_koff   = ((lane >> 3) & 1) * 8;

#define GEMM_ISSUE(c) do {                                                   \
        int k0_ = (c) * 32;                                                  \
        uint32_t sb_ = sbase + (((c) & 1) * STAGE_HW) * 2;                   \
        size_t gA0 = (size_t)(bm + ar0) * K + k0_ + akc * 8;                 \
        size_t gA1 = (size_t)(bm + ar1) * K + k0_ + akc * 8;                 \
        size_t gW  = (size_t)(bn + wr)  * K + k0_ + akc * 8;                 \
        cp_async16(sb_ + (ST_AHI + ar0 * GP + akc * 8) * 2, Ahi + gA0);      \
        cp_async16(sb_ + (ST_ALO + ar0 * GP + akc * 8) * 2, Alo + gA0);      \
        cp_async16(sb_ + (ST_AHI + ar1 * GP + akc * 8) * 2, Ahi + gA1);     \
        cp_async16(sb_ + (ST_ALO + ar1 * GP + akc * 8) * 2, Alo + gA1);     \
        cp_async16(sb_ + (ST_WHI + wr * GP + akc * 8) * 2, Whi + gW);        \
        cp_async16(sb_ + (ST_WLO + wr * GP + akc * 8) * 2, Wlo + gW);        \
    } while (0)

    GEMM_ISSUE(0); CP_COMMIT();

    for (int c = 0; c < nch; c++) {
        if (c + 1 < nch) { GEMM_ISSUE(c + 1); CP_COMMIT(); CP_WAIT1(); }
        else             { CP_WAIT0(); }
        __syncthreads();

        const uint32_t sb = sbase + ((c & 1) * STAGE_HW) * 2;
#pragma unroll
        for (int kk = 0; kk < 32; kk += 16) {
            uint32_t aHi[2][4], aLo[2][4], bHi[4][2], bLo[4][2];
#pragma unroll
            for (int mf = 0; mf < 2; mf++) {
                int hw = (wm * 32 + mf * 16 + a_row_in) * GP + kk + a_koff;
                ldsm_x4(aHi[mf], sb + (ST_AHI + hw) * 2);
                ldsm_x4(aLo[mf], sb + (ST_ALO + hw) * 2);
            }
#pragma unroll
            for (int p = 0; p < 2; p++) {
                int hw = (wn * 32 + p * 16 + b_row_in) * GP + kk + b_koff;
                uint32_t rh[4], rl[4];
                ldsm_x4(rh, sb + (ST_WHI + hw) * 2);
                ldsm_x4(rl, sb + (ST_WLO + hw) * 2);
                bHi[2 * p][0] = rh[0]; bHi[2 * p][1] = rh[1];
                bHi[2 * p + 1][0] = rh[2]; bHi[2 * p + 1][1] = rh[3];
                bLo[2 * p][0] = rl[0]; bLo[2 * p][1] = rl[1];
                bLo[2 * p + 1][0] = rl[2]; bLo[2 * p + 1][1] = rl[3];
            }
#pragma unroll
            for (int mf = 0; mf < 2; mf++)
#pragma unroll
                for (int nf = 0; nf < 4; nf++) {
                    mma16816(acc[mf][nf], aHi[mf], bHi[nf]);
                    mma16816(acc[mf][nf], aHi[mf], bLo[nf]);
                    mma16816(acc[mf][nf], aLo[mf], bHi[nf]);
                }
        }
        __syncthreads();
    }

    const int gq = lane >> 2;
    const int qt = lane & 3;
#pragma unroll
    for (int mf = 0; mf < 2; mf++) {
#pragma unroll
        for (int nf = 0; nf < 4; nf++) {
            int row0 = bm + wm * 32 + mf * 16 + gq;
            int col  = bn + wn * 32 + nf * 8 + qt * 2;
            *(float2*)(Cout + (size_t)row0 * N + col) =
                make_float2(acc[mf][nf][0], acc[mf][nf][1]);
            *(float2*)(Cout + (size_t)(row0 + 8) * N + col) =
                make_float2(acc[mf][nf][2], acc[mf][nf][3]);
        }
    }
}

// ===========================================================================
// RoPE + layout scatter, emitting fp32 (optional) AND bf16 hi/lo split
// ===========================================================================
__global__ void rope_scatter2(const float* __restrict__ raw,
                              const float* __restrict__ cosT,
                              const float* __restrict__ sinT,
                              float* __restrict__ dstF,
                              __nv_bfloat16* __restrict__ dstH,
                              __nv_bfloat16* __restrict__ dstL,
                              int heads, float scale, int doRope)
{
    const long long total = (long long)B_ * T_ * heads * (D_ / 2);
    long long p = (long long)blockIdx.x * blockDim.x + threadIdx.x;
    if (p >= total) return;

    const int n2 = heads * (D_ / 2);
    long long bt = p / n2;
    int r  = (int)(p % n2);
    int h  = r / (D_ / 2);
    int d  = (r % (D_ / 2)) * 2;
    int t  = (int)(bt % T_);
    int b  = (int)(bt / T_);

    const float* src = raw + bt * (size_t)(heads * D_) + h * D_ + d;
    float x1 = src[0];
    float x2 = src[1];
    float o1, o2;
    if (doRope) {
        float c1 = cosT[t * D_ + d],     s1 = sinT[t * D_ + d];
        float c2 = cosT[t * D_ + d + 1], s2 = sinT[t * D_ + d + 1];
        o1 = x1 * c1 - x2 * s1;
        o2 = x2 * c2 + x1 * s2;
    } else {
        o1 = x1; o2 = x2;
    }
    o1 *= scale; o2 *= scale;
    size_t oi = (((size_t)b * heads + h) * T_ + t) * D_ + d;
    if (dstF) { dstF[oi] = o1; dstF[oi + 1] = o2; }
    uint32_t hw, lw;
    split_pair(o1, o2, hw, lw);
    *(uint32_t*)((uint16_t*)dstH + oi) = hw;
    *(uint32_t*)((uint16_t*)dstL + oi) = lw;
}

// ===========================================================================
// Tensor-core causal flash attention (GQA), consuming pre-split bf16 hi/lo.
// Block = 64 q rows of one (b,h); 128 threads = 4 warps.
// ===========================================================================
#define FP 72
#define FK_HI 0
#define FK_LO 4608
#define FV_HI 9216
#define FV_LO 13824

__global__ __launch_bounds__(128)
void flash_mma(const __nv_bfloat16* __restrict__ Qh, const __nv_bfloat16* __restrict__ Ql,
               const __nv_bfloat16* __restrict__ Kh, const __nv_bfloat16* __restrict__ Kl,
               const __nv_bfloat16* __restrict__ Vh, const __nv_bfloat16* __restrict__ Vl,
               float* __restrict__ Oall)
{
    __shared__ __align__(16) uint16_t buf[18432];   // 36,864 bytes

    const int qb  = blockIdx.x;
    const int bh  = blockIdx.y;
    const int b   = bh >> 5;
    const int h   = bh & 31;
    const int kh  = h >> 3;
    const int tid = threadIdx.x;
    const int wm  = tid >> 5;
    const int lane = tid & 31;
    const int gq  = lane >> 2;
    const int qt  = lane & 3;
    const int q0  = qb * 64;

    const uint16_t* Qhp = (const uint16_t*)Qh + ((size_t)bh * T_ + q0) * D_;
    const uint16_t* Qlp = (const uint16_t*)Ql + ((size_t)bh * T_ + q0) * D_;
    const size_t kvoff = ((size_t)(b * HK_ + kh) * T_) * D_;
    const uint16_t* Khp = (const uint16_t*)Kh + kvoff;
    const uint16_t* Klp = (const uint16_t*)Kl + kvoff;
    const uint16_t* Vhp = (const uint16_t*)Vh + kvoff;
    const uint16_t* Vlp = (const uint16_t*)Vl + kvoff;

    const uint32_t sbase = smem_u32(buf);

    // ---- cp.async Q hi/lo tiles (64 x 64 bf16 each) ----
    {
        int row = tid >> 1;                      // 0..63
        int kc  = tid & 1;                       // 2 chunk-pairs per row? no:
        // 8 chunks per row (128B); 128 threads -> each does 4 chunks of 2 rows
#pragma unroll
        for (int g = 0; g < 4; g++) {
            int ch  = kc * 4 + g;                // chunk 0..7
            size_t src = (size_t)row * D_ + ch * 8;
            uint32_t dsthw = row * FP + ch * 8;
            cp_async16(sbase + (FK_HI + dsthw) * 2, Qhp + src);
            cp_async16(sbase + (FK_LO + dsthw) * 2, Qlp + src);
        }
    }
    CP_COMMIT(); CP_WAIT0();
    __syncthreads();

    const int a_row = ((lane >> 3) & 1) * 8 + (lane & 7);
    const int a_k   = (lane >> 4) * 8;
    const int b_row = ((lane >> 4) & 1) * 8 + (lane & 7);
    const int b_k   = ((lane >> 3) & 1) * 8;

    uint32_t qhi[4][4], qlo[4][4];
#pragma unroll
    for (int dk = 0; dk < 4; dk++) {
        int hw = (wm * 16 + a_row) * FP + dk * 16 + a_k;
        ldsm_x4(qhi[dk], sbase + 2 * (FK_HI + hw));
        ldsm_x4(qlo[dk], sbase + 2 * (FK_LO + hw));
    }
    __syncthreads();

    float m0 = -1e30f, m1 = -1e30f, l0 = 0.f, l1 = 0.f;
    float o[8][4];
#pragma unroll
    for (int nf = 0; nf < 8; nf++)
#pragma unroll
        for (int q = 0; q < 4; q++) o[nf][q] = 0.f;

    for (int kb = 0; kb <= qb; kb++) {
        // ---- cp.async K hi/lo tile ----
        {
            int row = tid >> 1;
            int kc  = tid & 1;
#pragma unroll
            for (int g = 0; g < 4; g++) {
                int ch  = kc * 4 + g;
                size_t src = (size_t)(kb * 64 + row) * D_ + ch * 8;
                uint32_t dsthw = row * FP + ch * 8;
                cp_async16(sbase + (FK_HI + dsthw) * 2, Khp + src);
                cp_async16(sbase + (FK_LO + dsthw) * 2, Klp + src);
            }
        }
        CP_COMMIT();

        // ---- V tile: LDG bf16 + transpose-pack into [d][s] (no float math) ----
#pragma unroll
        for (int u2 = 0; u2 < 2; u2++) {
            int u  = tid + u2 * 128;
            int s0 = 2 * (u & 31);
            int d0 = 8 * (u >> 5);
            size_t g0 = (size_t)(kb * 64 + s0) * D_ + d0;
            uint4 h0 = *(const uint4*)(Vhp + g0);
            uint4 h1 = *(const uint4*)(Vhp + g0 + D_);
            uint4 l0v = *(const uint4*)(Vlp + g0);
            uint4 l1v = *(const uint4*)(Vlp + g0 + D_);
            const uint32_t* a0 = (const uint32_t*)&h0;
            const uint32_t* a1 = (const uint32_t*)&h1;
            const uint32_t* c0 = (const uint32_t*)&l0v;
            const uint32_t* c1 = (const uint32_t*)&l1v;
#pragma unroll
            for (int j = 0; j < 4; j++) {
                uint32_t ah = a0[j], bhw = a1[j];
                uint32_t al = c0[j], blw = c1[j];
                int d = d0 + 2 * j;
                *(uint32_t*)&buf[FV_HI + d * FP + s0] = (ah & 0xffffu) | (bhw << 16);
                *(uint32_t*)&buf[FV_HI + (d + 1) * FP + s0] = (ah >> 16) | (bhw & 0xffff0000u);
                *(uint32_t*)&buf[FV_LO + d * FP + s0] = (al & 0xffffu) | (blw << 16);
                *(uint32_t*)&buf[FV_LO + (d + 1) * FP + s0] = (al >> 16) | (blw & 0xffff0000u);
            }
        }
        CP_WAIT0();
        __syncthreads();

        // ---- S = Q K^T (3-way split) ----
        float s[8][4];
#pragma unroll
        for (int nf = 0; nf < 8; nf++)
#pragma unroll
            for (int q = 0; q < 4; q++) s[nf][q] = 0.f;

#pragma unroll
        for (int dk = 0; dk < 4; dk++) {
            uint32_t kfh[4][4], kfl[4][4];
#pragma unroll
            for (int g = 0; g < 4; g++) {
                int hw = (16 * g + b_row) * FP + dk * 16 + b_k;
                ldsm_x4(kfh[g], sbase + 2 * (FK_HI + hw));
                ldsm_x4(kfl[g], sbase + 2 * (FK_LO + hw));
            }
#pragma unroll
            for (int g = 0; g < 4; g++) {
                mma16816(s[2 * g],     qhi[dk], &kfh[g][0]);
                mma16816(s[2 * g],     qhi[dk], &kfl[g][0]);
                mma16816(s[2 * g],     qlo[dk], &kfh[g][0]);
                mma16816(s[2 * g + 1], qhi[dk], &kfh[g][2]);
                mma16816(s[2 * g + 1], qhi[dk], &kfl[g][2]);
                mma16816(s[2 * g + 1], qlo[dk], &kfh[g][2]);
            }
        }

        if (kb == qb) {
            int r0g = 16 * wm + gq;
            int r1g = r0g + 8;
#pragma unroll
            for (int nf = 0; nf < 8; nf++) {
                int c = nf * 8 + 2 * qt;
                if (c     > r0g) s[nf][0] = -1e30f;
                if (c + 1 > r0g) s[nf][1] = -1e30f;
                if (c     > r1g) s[nf][2] = -1e30f;
                if (c + 1 > r1g) s[nf][3] = -1e30f;
            }
        }

        // ---- online softmax ----
        float mx0 = -1e30f, mx1 = -1e30f;
#pragma unroll
        for (int nf = 0; nf < 8; nf++) {
            mx0 = fmaxf(mx0, fmaxf(s[nf][0], s[nf][1]));
            mx1 = fmaxf(mx1, fmaxf(s[nf][2], s[nf][3]));
        }
        mx0 = fmaxf(mx0, __shfl_xor_sync(0xffffffffu, mx0, 1));
        mx0 = fmaxf(mx0, __shfl_xor_sync(0xffffffffu, mx0, 2));
        mx1 = fmaxf(mx1, __shfl_xor_sync(0xffffffffu, mx1, 1));
        mx1 = fmaxf(mx1, __shfl_xor_sync(0xffffffffu, mx1, 2));
        float mn0 = fmaxf(m0, mx0), mn1 = fmaxf(m1, mx1);
        float al0 = __expf(m0 - mn0), al1 = __expf(m1 - mn1);
        float sum0 = 0.f, sum1 = 0.f;
#pragma unroll
        for (int nf = 0; nf < 8; nf++) {
            s[nf][0] = __expf(s[nf][0] - mn0);
            s[nf][1] = __expf(s[nf][1] - mn0);
            s[nf][2] = __expf(s[nf][2] - mn1);
            s[nf][3] = __expf(s[nf][3] - mn1);
            sum0 += s[nf][0] + s[nf][1];
            sum1 += s[nf][2] + s[nf][3];
        }
        sum0 += __shfl_xor_sync(0xffffffffu, sum0, 1);
        sum0 += __shfl_xor_sync(0xffffffffu, sum0, 2);
        sum1 += __shfl_xor_sync(0xffffffffu, sum1, 1);
        sum1 += __shfl_xor_sync(0xffffffffu, sum1, 2);
        l0 = l0 * al0 + sum0;  m0 = mn0;
        l1 = l1 * al1 + sum1;  m1 = mn1;
#pragma unroll
        for (int nf = 0; nf < 8; nf++) {
            o[nf][0] *= al0; o[nf][1] *= al0;
            o[nf][2] *= al1; o[nf][3] *= al1;
        }

        uint32_t phi[4][4], plo[4][4];
#pragma unroll
        for (int kc = 0; kc < 4; kc++) {
            split_pair(s[2 * kc][0],     s[2 * kc][1],     phi[kc][0], plo[kc][0]);
            split_pair(s[2 * kc][2],     s[2 * kc][3],     phi[kc][1], plo[kc][1]);
            split_pair(s[2 * kc + 1][0], s[2 * kc + 1][1], phi[kc][2], plo[kc][2]);
            split_pair(s[2 * kc + 1][2], s[2 * kc + 1][3], phi[kc][3], plo[kc][3]);
        }

#pragma unroll
        for (int kc = 0; kc < 4; kc++) {
            uint32_t vfh[4][4], vfl[4][4];
#pragma unroll
            for (int g = 0; g < 4; g++) {
                int hw = (16 * g + b_row) * FP + kc * 16 + b_k;
                ldsm_x4(vfh[g], sbase + 2 * (FV_HI + hw));
                ldsm_x4(vfl[g], sbase + 2 * (FV_LO + hw));
            }
#pragma unroll
            for (int g = 0; g < 4; g++) {
                mma16816(o[2 * g],     phi[kc], &vfh[g][0]);
                mma16816(o[2 * g],     phi[kc], &vfl[g][0]);
                mma16816(o[2 * g],     plo[kc], &vfh[g][0]);
                mma16816(o[2 * g + 1], phi[kc], &vfh[g][2]);
                mma16816(o[2 * g + 1], phi[kc], &vfl[g][2]);
                mma16816(o[2 * g + 1], plo[kc], &vfh[g][2]);
            }
        }
        __syncthreads();
    }

    float inv0 = 1.0f / l0, inv1 = 1.0f / l1;
    int row0 = q0 + wm * 16 + gq;
    float* dst0 = Oall + ((size_t)b * T_ + row0) * (H_ * D_) + h * D_;
    float* dst1 = dst0 + (size_t)8 * (H_ * D_);
#pragma unroll
    for (int nf = 0; nf < 8; nf++) {
        int c = nf * 8 + 2 * qt;
        *(float2*)(dst0 + c) = make_float2(o[nf][0] * inv0, o[nf][1] * inv0);
        *(float2*)(dst1 + c) = make_float2(o[nf][2] * inv1, o[nf][3] * inv1);
    }
}

// ===========================================================================
extern "C" void kernel_launch(void* const* d_in, const int* in_sizes, int n_in,
                              void* d_out, int out_size)
{
    const float* x    = (const float*)d_in[0];
    const float* cosT = (const float*)d_in[1];
    const float* sinT = (const float*)d_in[2];
    const float* wq   = (const float*)d_in[3];
    const float* wk   = (const float*)d_in[4];
    const float* wv   = (const float*)d_in[5];
    const float* wo   = (const float*)d_in[6];

    float* out   = (float*)d_out;
    float* out_k = out   + (size_t)B_ * T_ * C_;
    float* out_v = out_k + (size_t)B_ * HK_ * T_ * D_;

    float *qraw, *kraw, *vraw, *obuf;
    cudaGetSymbolAddress((void**)&qraw, g_qraw);
    cudaGetSymbolAddress((void**)&kraw, g_kraw);
    cudaGetSymbolAddress((void**)&vraw, g_vraw);
    cudaGetSymbolAddress((void**)&obuf, g_o);

    __nv_bfloat16 *xh, *xl, *oh, *ol, *wqh, *wql, *wkh, *wkl, *wvh, *wvl, *woh, *wol;
    __nv_bfloat16 *qh, *ql, *kh, *kl, *vh, *vl;
    cudaGetSymbolAddress((void**)&xh, g_xh);   cudaGetSymbolAddress((void**)&xl, g_xl);
    cudaGetSymbolAddress((void**)&oh, g_oh);   cudaGetSymbolAddress((void**)&ol, g_ol);
    cudaGetSymbolAddress((void**)&wqh, g_wqh); cudaGetSymbolAddress((void**)&wql, g_wql);
    cudaGetSymbolAddress((void**)&wkh, g_wkh); cudaGetSymbolAddress((void**)&wkl, g_wkl);
    cudaGetSymbolAddress((void**)&wvh, g_wvh); cudaGetSymbolAddress((void**)&wvl, g_wvl);
    cudaGetSymbolAddress((void**)&woh, g_woh); cudaGetSymbolAddress((void**)&wol, g_wol);
    cudaGetSymbolAddress((void**)&qh, g_qh);   cudaGetSymbolAddress((void**)&ql, g_ql);
    cudaGetSymbolAddress((void**)&kh, g_kh);   cudaGetSymbolAddress((void**)&kl, g_kl);
    cudaGetSymbolAddress((void**)&vh, g_vh);   cudaGetSymbolAddress((void**)&vl, g_vl);

    cudaFuncSetAttribute(gemm_split,
                         cudaFuncAttributeMaxDynamicSharedMemorySize, GEMM2_SMEM);

    dim3 blk(256);

    // ---- pre-split inputs into bf16 hi/lo ----
    {
        int nx = (MROWS * C_) / 8;
        int nw = ((H_ * D_) * C_) / 8;
        int ns = ((HK_ * D_) * C_) / 8;
        split_f32<<<(nx + 255) / 256, 256>>>(x,  xh,  xl,  nx);
        split_f32<<<(nw + 255) / 256, 256>>>(wq, wqh, wql, nw);
        split_f32<<<(ns + 255) / 256, 256>>>(wk, wkh, wkl, ns);
        split_f32<<<(ns + 255) / 256, 256>>>(wv, wvh, wvl, ns);
        split_f32<<<(nw + 255) / 256, 256>>>(wo, woh, wol, nw);
    }

    // ---- projections ----
    gemm_split<<<dim3((H_ * D_) / 64, MROWS / 128), blk, GEMM2_SMEM>>>(
        xh, xl, wqh, wql, qraw, MROWS, H_ * D_, C_);
    gemm_split<<<dim3((HK_ * D_) / 64, MROWS / 128), blk, GEMM2_SMEM>>>(
        xh, xl, wkh, wkl, kraw, MROWS, HK_ * D_, C_);
    gemm_split<<<dim3((HK_ * D_) / 64, MROWS / 128), blk, GEMM2_SMEM>>>(
        xh, xl, wvh, wvl, vraw, MROWS, HK_ * D_, C_);

    // ---- RoPE + layout + split ----
    {
        long long pq = (long long)B_ * T_ * H_ * (D_ / 2);
        long long pk = (long long)B_ * T_ * HK_ * (D_ / 2);
        rope_scatter2<<<(unsigned)((pq + 255) / 256), 256>>>(
            qraw, cosT, sinT, (float*)nullptr, qh, ql, H_, 0.125f, 1);
        rope_scatter2<<<(unsigned)((pk + 255) / 256), 256>>>(
            kraw, cosT, sinT, out_k, kh, kl, HK_, 1.0f, 1);
        rope_scatter2<<<(unsigned)((pk + 255) / 256), 256>>>(
            vraw, cosT, sinT, out_v, vh, vl, HK_, 1.0f, 0);
    }

    // ---- flash attention ----
    flash_mma<<<dim3(T_ / 64, B_ * H_), 128>>>(qh, ql, kh, kl, vh, vl, obuf);

    // ---- split attention output, then output projection ----
    {
        int no = (MROWS * C_) / 8;
        split_f32<<<(no + 255) / 256, 256>>>(obuf, oh, ol, no);
    }
    gemm_split<<<dim3(C_ / 64, MROWS / 128), blk, GEMM2_SMEM>>>(
        oh, ol, woh, wol, out, MROWS, C_, H_ * D_);
}

// round 9
// speedup vs baseline: 2.6134x; 1.0510x over previous
#include <cuda_runtime.h>
#include <cuda_bf16.h>
#include <math.h>
#include <stdint.h>

// Problem constants
#define B_   2
#define T_   2048
#define C_   2048
#define H_   32
#define HK_  4
#define D_   64
#define MROWS (B_ * T_)          // 4096

// ---------------- scratch (static device globals; no allocation) ----------
__device__ float g_qraw[(long long)MROWS * (H_ * D_)];
__device__ float g_kraw[(long long)MROWS * (HK_ * D_)];
__device__ float g_vraw[(long long)MROWS * (HK_ * D_)];

__device__ __nv_bfloat16 g_xh[(long long)MROWS * C_],  g_xl[(long long)MROWS * C_];
__device__ __nv_bfloat16 g_oh[(long long)MROWS * C_],  g_ol[(long long)MROWS * C_];
__device__ __nv_bfloat16 g_wqh[(long long)(H_*D_) * C_],  g_wql[(long long)(H_*D_) * C_];
__device__ __nv_bfloat16 g_wkh[(long long)(HK_*D_) * C_], g_wkl[(long long)(HK_*D_) * C_];
__device__ __nv_bfloat16 g_wvh[(long long)(HK_*D_) * C_], g_wvl[(long long)(HK_*D_) * C_];
__device__ __nv_bfloat16 g_woh[(long long)C_ * (H_*D_)],  g_wol[(long long)C_ * (H_*D_)];
__device__ __nv_bfloat16 g_qh[(long long)B_*H_*T_*D_],  g_ql[(long long)B_*H_*T_*D_];
__device__ __nv_bfloat16 g_kh[(long long)B_*HK_*T_*D_], g_kl[(long long)B_*HK_*T_*D_];
__device__ __nv_bfloat16 g_vh[(long long)B_*HK_*T_*D_], g_vl[(long long)B_*HK_*T_*D_];

// ===========================================================================
// helpers
// ===========================================================================
__device__ __forceinline__ uint32_t smem_u32(const void* p) {
    uint32_t a;
    asm("{ .reg .u64 t; cvta.to.shared.u64 t, %1; cvt.u32.u64 %0, t; }"
        : "=r"(a) : "l"(p));
    return a;
}
__device__ __forceinline__ void ldsm_x4(uint32_t* r, uint32_t addr) {
    asm volatile("ldmatrix.sync.aligned.m8n8.x4.shared.b16 {%0,%1,%2,%3}, [%4];"
        : "=r"(r[0]), "=r"(r[1]), "=r"(r[2]), "=r"(r[3]) : "r"(addr));
}
__device__ __forceinline__ void mma16816(float* c, const uint32_t* a, const uint32_t* b) {
    asm volatile(
        "mma.sync.aligned.m16n8k16.row.col.f32.bf16.bf16.f32 "
        "{%0,%1,%2,%3}, {%4,%5,%6,%7}, {%8,%9}, {%0,%1,%2,%3};"
        : "+f"(c[0]), "+f"(c[1]), "+f"(c[2]), "+f"(c[3])
        : "r"(a[0]), "r"(a[1]), "r"(a[2]), "r"(a[3]), "r"(b[0]), "r"(b[1]));
}
__device__ __forceinline__ void split_pair(float a, float b, uint32_t& hi, uint32_t& lo) {
    __nv_bfloat162 h = __floats2bfloat162_rn(a, b);
    float ra = a - __bfloat162float(h.x);
    float rb = b - __bfloat162float(h.y);
    __nv_bfloat162 l = __floats2bfloat162_rn(ra, rb);
    hi = *(uint32_t*)&h;
    lo = *(uint32_t*)&l;
}
__device__ __forceinline__ void cp_async16(uint32_t dst, const void* src) {
    asm volatile("cp.async.cg.shared.global [%0], [%1], 16;" :: "r"(dst), "l"(src));
}
#define CP_COMMIT() asm volatile("cp.async.commit_group;" ::: "memory")
#define CP_WAIT1()  asm volatile("cp.async.wait_group 1;" ::: "memory")
#define CP_WAIT0()  asm volatile("cp.async.wait_group 0;" ::: "memory")

// ===========================================================================
// fp32 -> bf16 hi/lo global split
// ===========================================================================
__global__ void split_f32(const float* __restrict__ src,
                          __nv_bfloat16* __restrict__ hi,
                          __nv_bfloat16* __restrict__ lo, int n8)
{
    int i = blockIdx.x * blockDim.x + threadIdx.x;
    if (i >= n8) return;
    const float4* p = (const float4*)src + 2 * (size_t)i;
    float4 f0 = p[0], f1 = p[1];
    uint4 h, l;
    split_pair(f0.x, f0.y, h.x, l.x);
    split_pair(f0.z, f0.w, h.y, l.y);
    split_pair(f1.x, f1.y, h.z, l.z);
    split_pair(f1.z, f1.w, h.w, l.w);
    ((uint4*)hi)[i] = h;
    ((uint4*)lo)[i] = l;
}

// ===========================================================================
// GEMM core: C[*,N] block (128 x 128) = (Ah+Al) @ (Wh+Wl)^T, bf16x3, K=2048.
// 256 threads = 8 warps (4m x 2n), warp tile 32x64. cp.async 2-stage.
// ===========================================================================
#define GP 40
#define ST_AHI 0
#define ST_ALO (128 * GP)          // 5120
#define ST_WHI (2 * 128 * GP)      // 10240
#define ST_WLO (3 * 128 * GP)      // 15360
#define STAGE_HW (4 * 128 * GP)    // 20480 hw = 40960 B
#define GEMM_SMEM (2 * STAGE_HW * 2)   // 81920 B

__device__ __forceinline__ void gemm_core(
    const uint16_t* __restrict__ Ahi, const uint16_t* __restrict__ Alo,
    const uint16_t* __restrict__ Whi, const uint16_t* __restrict__ Wlo,
    float* __restrict__ Cout, int N, int bm, int bn, uint16_t* smem)
{
    const int K = C_;
    const uint32_t sbase = smem_u32(smem);
    const int tid  = threadIdx.x;
    const int wid  = tid >> 5;
    const int lane = tid & 31;
    const int wm   = wid & 3;
    const int wn   = wid >> 2;

    float acc[2][8][4];
#pragma unroll
    for (int i = 0; i < 2; i++)
#pragma unroll
        for (int j = 0; j < 8; j++)
#pragma unroll
            for (int q = 0; q < 4; q++) acc[i][j][q] = 0.f;

    const int a_row_in = ((lane >> 3) & 1) * 8 + (lane & 7);
    const int a_koff   = (lane >> 4) * 8;
    const int b_row_in = ((lane >> 4) & 1) * 8 + (lane & 7);
    const int b_koff   = ((lane >> 3) & 1) * 8;

#define GEMM_ISSUE(c) do {                                                    \
        int k0_ = (c) * 32;                                                   \
        uint32_t sb_ = sbase + (((c) & 1) * STAGE_HW) * 2;                     \
        _Pragma("unroll")                                                      \
        for (int r_ = 0; r_ < 2; r_++) {                                      \
            int e_  = tid + r_ * 256;                                          \
            int row = e_ >> 2;                                                 \
            int ch  = e_ & 3;                                                  \
            size_t gA = (size_t)(bm + row) * K + k0_ + ch * 8;                 \
            size_t gW = (size_t)(bn + row) * K + k0_ + ch * 8;                 \
            uint32_t hwo = (row * GP + ch * 8) * 2;                            \
            cp_async16(sb_ + ST_AHI * 2 + hwo, Ahi + gA);                      \
            cp_async16(sb_ + ST_ALO * 2 + hwo, Alo + gA);                      \
            cp_async16(sb_ + ST_WHI * 2 + hwo, Whi + gW);                      \
            cp_async16(sb_ + ST_WLO * 2 + hwo, Wlo + gW);                      \
        }                                                                      \
    } while (0)

    GEMM_ISSUE(0); CP_COMMIT();

    const int nch = K / 32;
    for (int c = 0; c < nch; c++) {
        if (c + 1 < nch) { GEMM_ISSUE(c + 1); CP_COMMIT(); CP_WAIT1(); }
        else             { CP_WAIT0(); }
        __syncthreads();

        const uint32_t sb = sbase + ((c & 1) * STAGE_HW) * 2;
#pragma unroll
        for (int kk = 0; kk < 32; kk += 16) {
            uint32_t aHi[2][4], aLo[2][4], bHi[8][2], bLo[8][2];
#pragma unroll
            for (int mf = 0; mf < 2; mf++) {
                int hw = (wm * 32 + mf * 16 + a_row_in) * GP + kk + a_koff;
                ldsm_x4(aHi[mf], sb + (ST_AHI + hw) * 2);
                ldsm_x4(aLo[mf], sb + (ST_ALO + hw) * 2);
            }
#pragma unroll
            for (int p = 0; p < 4; p++) {
                int hw = (wn * 64 + p * 16 + b_row_in) * GP + kk + b_koff;
                uint32_t rh[4], rl[4];
                ldsm_x4(rh, sb + (ST_WHI + hw) * 2);
                ldsm_x4(rl, sb + (ST_WLO + hw) * 2);
                bHi[2 * p][0] = rh[0]; bHi[2 * p][1] = rh[1];
                bHi[2 * p + 1][0] = rh[2]; bHi[2 * p + 1][1] = rh[3];
                bLo[2 * p][0] = rl[0]; bLo[2 * p][1] = rl[1];
                bLo[2 * p + 1][0] = rl[2]; bLo[2 * p + 1][1] = rl[3];
            }
#pragma unroll
            for (int mf = 0; mf < 2; mf++)
#pragma unroll
                for (int nf = 0; nf < 8; nf++) {
                    mma16816(acc[mf][nf], aHi[mf], bHi[nf]);
                    mma16816(acc[mf][nf], aHi[mf], bLo[nf]);
                    mma16816(acc[mf][nf], aLo[mf], bHi[nf]);
                }
        }
        __syncthreads();
    }

    const int gq = lane >> 2;
    const int qt = lane & 3;
#pragma unroll
    for (int mf = 0; mf < 2; mf++) {
#pragma unroll
        for (int nf = 0; nf < 8; nf++) {
            int row0 = bm + wm * 32 + mf * 16 + gq;
            int col  = bn + wn * 64 + nf * 8 + qt * 2;
            *(float2*)(Cout + (size_t)row0 * N + col) =
                make_float2(acc[mf][nf][0], acc[mf][nf][1]);
            *(float2*)(Cout + (size_t)(row0 + 8) * N + col) =
                make_float2(acc[mf][nf][2], acc[mf][nf][3]);
        }
    }
#undef GEMM_ISSUE
}

// Fused q/k/v projection: grid.x regions [0,16)=wq, [16,18)=wk, [18,20)=wv
__global__ __launch_bounds__(256)
void gemm_proj(const __nv_bfloat16* __restrict__ xh, const __nv_bfloat16* __restrict__ xl,
               const __nv_bfloat16* __restrict__ wqh, const __nv_bfloat16* __restrict__ wql,
               const __nv_bfloat16* __restrict__ wkh, const __nv_bfloat16* __restrict__ wkl,
               const __nv_bfloat16* __restrict__ wvh, const __nv_bfloat16* __restrict__ wvl,
               float* __restrict__ qraw, float* __restrict__ kraw, float* __restrict__ vraw)
{
    extern __shared__ __align__(16) uint16_t smem[];
    const int bx = blockIdx.x;
    const int bm = blockIdx.y * 128;
    const uint16_t *Whi, *Wlo;
    float* Cout;
    int N, bn;
    if (bx < 16)      { Whi = (const uint16_t*)wqh; Wlo = (const uint16_t*)wql;
                        Cout = qraw; N = H_ * D_;  bn = bx * 128; }
    else if (bx < 18) { Whi = (const uint16_t*)wkh; Wlo = (const uint16_t*)wkl;
                        Cout = kraw; N = HK_ * D_; bn = (bx - 16) * 128; }
    else              { Whi = (const uint16_t*)wvh; Wlo = (const uint16_t*)wvl;
                        Cout = vraw; N = HK_ * D_; bn = (bx - 18) * 128; }
    gemm_core((const uint16_t*)xh, (const uint16_t*)xl, Whi, Wlo, Cout, N, bm, bn, smem);
}

// Output projection
__global__ __launch_bounds__(256)
void gemm_out(const __nv_bfloat16* __restrict__ oh, const __nv_bfloat16* __restrict__ ol,
              const __nv_bfloat16* __restrict__ woh, const __nv_bfloat16* __restrict__ wol,
              float* __restrict__ out)
{
    extern __shared__ __align__(16) uint16_t smem[];
    gemm_core((const uint16_t*)oh, (const uint16_t*)ol,
              (const uint16_t*)woh, (const uint16_t*)wol,
              out, C_, blockIdx.y * 128, blockIdx.x * 128, smem);
}

// ===========================================================================
// RoPE + layout scatter, emitting fp32 (optional) AND bf16 hi/lo split
// ===========================================================================
__global__ void rope_scatter2(const float* __restrict__ raw,
                              const float* __restrict__ cosT,
                              const float* __restrict__ sinT,
                              float* __restrict__ dstF,
                              __nv_bfloat16* __restrict__ dstH,
                              __nv_bfloat16* __restrict__ dstL,
                              int heads, float scale, int doRope)
{
    const long long total = (long long)B_ * T_ * heads * (D_ / 2);
    long long p = (long long)blockIdx.x * blockDim.x + threadIdx.x;
    if (p >= total) return;

    const int n2 = heads * (D_ / 2);
    long long bt = p / n2;
    int r  = (int)(p % n2);
    int h  = r / (D_ / 2);
    int d  = (r % (D_ / 2)) * 2;
    int t  = (int)(bt % T_);
    int b  = (int)(bt / T_);

    const float* src = raw + bt * (size_t)(heads * D_) + h * D_ + d;
    float x1 = src[0];
    float x2 = src[1];
    float o1, o2;
    if (doRope) {
        float c1 = cosT[t * D_ + d],     s1 = sinT[t * D_ + d];
        float c2 = cosT[t * D_ + d + 1], s2 = sinT[t * D_ + d + 1];
        o1 = x1 * c1 - x2 * s1;
        o2 = x2 * c2 + x1 * s2;
    } else {
        o1 = x1; o2 = x2;
    }
    o1 *= scale; o2 *= scale;
    size_t oi = (((size_t)b * heads + h) * T_ + t) * D_ + d;
    if (dstF) { dstF[oi] = o1; dstF[oi + 1] = o2; }
    uint32_t hw, lw;
    split_pair(o1, o2, hw, lw);
    *(uint32_t*)((uint16_t*)dstH + oi) = hw;
    *(uint32_t*)((uint16_t*)dstL + oi) = lw;
}

// ===========================================================================
// Tensor-core causal flash attention (GQA), pre-split bf16 hi/lo in & out.
// ===========================================================================
#define FP 72
#define FK_HI 0
#define FK_LO 4608
#define FV_HI 9216
#define FV_LO 13824

__global__ __launch_bounds__(128)
void flash_mma(const __nv_bfloat16* __restrict__ Qh, const __nv_bfloat16* __restrict__ Ql,
               const __nv_bfloat16* __restrict__ Kh, const __nv_bfloat16* __restrict__ Kl,
               const __nv_bfloat16* __restrict__ Vh, const __nv_bfloat16* __restrict__ Vl,
               __nv_bfloat16* __restrict__ Oh, __nv_bfloat16* __restrict__ Ol)
{
    __shared__ __align__(16) uint16_t buf[18432];

    const int qb  = blockIdx.x;
    const int bh  = blockIdx.y;
    const int b   = bh >> 5;
    const int h   = bh & 31;
    const int kh  = h >> 3;
    const int tid = threadIdx.x;
    const int wm  = tid >> 5;
    const int lane = tid & 31;
    const int gq  = lane >> 2;
    const int qt  = lane & 3;
    const int q0  = qb * 64;

    const uint16_t* Qhp = (const uint16_t*)Qh + ((size_t)bh * T_ + q0) * D_;
    const uint16_t* Qlp = (const uint16_t*)Ql + ((size_t)bh * T_ + q0) * D_;
    const size_t kvoff = ((size_t)(b * HK_ + kh) * T_) * D_;
    const uint16_t* Khp = (const uint16_t*)Kh + kvoff;
    const uint16_t* Klp = (const uint16_t*)Kl + kvoff;
    const uint16_t* Vhp = (const uint16_t*)Vh + kvoff;
    const uint16_t* Vlp = (const uint16_t*)Vl + kvoff;

    const uint32_t sbase = smem_u32(buf);

    // ---- cp.async Q hi/lo tiles ----
    {
        int row = tid >> 1;
        int kc  = tid & 1;
#pragma unroll
        for (int g = 0; g < 4; g++) {
            int ch  = kc * 4 + g;
            size_t src = (size_t)row * D_ + ch * 8;
            uint32_t dsthw = row * FP + ch * 8;
            cp_async16(sbase + (FK_HI + dsthw) * 2, Qhp + src);
            cp_async16(sbase + (FK_LO + dsthw) * 2, Qlp + src);
        }
    }
    CP_COMMIT(); CP_WAIT0();
    __syncthreads();

    const int a_row = ((lane >> 3) & 1) * 8 + (lane & 7);
    const int a_k   = (lane >> 4) * 8;
    const int b_row = ((lane >> 4) & 1) * 8 + (lane & 7);
    const int b_k   = ((lane >> 3) & 1) * 8;

    uint32_t qhi[4][4], qlo[4][4];
#pragma unroll
    for (int dk = 0; dk < 4; dk++) {
        int hw = (wm * 16 + a_row) * FP + dk * 16 + a_k;
        ldsm_x4(qhi[dk], sbase + 2 * (FK_HI + hw));
        ldsm_x4(qlo[dk], sbase + 2 * (FK_LO + hw));
    }
    __syncthreads();

    float m0 = -1e30f, m1 = -1e30f, l0 = 0.f, l1 = 0.f;
    float o[8][4];
#pragma unroll
    for (int nf = 0; nf < 8; nf++)
#pragma unroll
        for (int q = 0; q < 4; q++) o[nf][q] = 0.f;

    for (int kb = 0; kb <= qb; kb++) {
        {
            int row = tid >> 1;
            int kc  = tid & 1;
#pragma unroll
            for (int g = 0; g < 4; g++) {
                int ch  = kc * 4 + g;
                size_t src = (size_t)(kb * 64 + row) * D_ + ch * 8;
                uint32_t dsthw = row * FP + ch * 8;
                cp_async16(sbase + (FK_HI + dsthw) * 2, Khp + src);
                cp_async16(sbase + (FK_LO + dsthw) * 2, Klp + src);
            }
        }
        CP_COMMIT();

        // V tile: LDG + transpose-pack into [d][s]
#pragma unroll
        for (int u2 = 0; u2 < 2; u2++) {
            int u  = tid + u2 * 128;
            int s0 = 2 * (u & 31);
            int d0 = 8 * (u >> 5);
            size_t g0 = (size_t)(kb * 64 + s0) * D_ + d0;
            uint4 h0 = *(const uint4*)(Vhp + g0);
            uint4 h1 = *(const uint4*)(Vhp + g0 + D_);
            uint4 l0v = *(const uint4*)(Vlp + g0);
            uint4 l1v = *(const uint4*)(Vlp + g0 + D_);
            const uint32_t* a0 = (const uint32_t*)&h0;
            const uint32_t* a1 = (const uint32_t*)&h1;
            const uint32_t* c0 = (const uint32_t*)&l0v;
            const uint32_t* c1 = (const uint32_t*)&l1v;
#pragma unroll
            for (int j = 0; j < 4; j++) {
                uint32_t ah = a0[j], bhw = a1[j];
                uint32_t al = c0[j], blw = c1[j];
                int d = d0 + 2 * j;
                *(uint32_t*)&buf[FV_HI + d * FP + s0] = (ah & 0xffffu) | (bhw << 16);
                *(uint32_t*)&buf[FV_HI + (d + 1) * FP + s0] = (ah >> 16) | (bhw & 0xffff0000u);
                *(uint32_t*)&buf[FV_LO + d * FP + s0] = (al & 0xffffu) | (blw << 16);
                *(uint32_t*)&buf[FV_LO + (d + 1) * FP + s0] = (al >> 16) | (blw & 0xffff0000u);
            }
        }
        CP_WAIT0();
        __syncthreads();

        // ---- S = Q K^T (3-way split) ----
        float s[8][4];
#pragma unroll
        for (int nf = 0; nf < 8; nf++)
#pragma unroll
            for (int q = 0; q < 4; q++) s[nf][q] = 0.f;

#pragma unroll
        for (int dk = 0; dk < 4; dk++) {
            uint32_t kfh[4][4], kfl[4][4];
#pragma unroll
            for (int g = 0; g < 4; g++) {
                int hw = (16 * g + b_row) * FP + dk * 16 + b_k;
                ldsm_x4(kfh[g], sbase + 2 * (FK_HI + hw));
                ldsm_x4(kfl[g], sbase + 2 * (FK_LO + hw));
            }
#pragma unroll
            for (int g = 0; g < 4; g++) {
                mma16816(s[2 * g],     qhi[dk], &kfh[g][0]);
                mma16816(s[2 * g],     qhi[dk], &kfl[g][0]);
                mma16816(s[2 * g],     qlo[dk], &kfh[g][0]);
                mma16816(s[2 * g + 1], qhi[dk], &kfh[g][2]);
                mma16816(s[2 * g + 1], qhi[dk], &kfl[g][2]);
                mma16816(s[2 * g + 1], qlo[dk], &kfh[g][2]);
            }
        }

        if (kb == qb) {
            int r0g = 16 * wm + gq;
            int r1g = r0g + 8;
#pragma unroll
            for (int nf = 0; nf < 8; nf++) {
                int c = nf * 8 + 2 * qt;
                if (c     > r0g) s[nf][0] = -1e30f;
                if (c + 1 > r0g) s[nf][1] = -1e30f;
                if (c     > r1g) s[nf][2] = -1e30f;
                if (c + 1 > r1g) s[nf][3] = -1e30f;
            }
        }

        float mx0 = -1e30f, mx1 = -1e30f;
#pragma unroll
        for (int nf = 0; nf < 8; nf++) {
            mx0 = fmaxf(mx0, fmaxf(s[nf][0], s[nf][1]));
            mx1 = fmaxf(mx1, fmaxf(s[nf][2], s[nf][3]));
        }
        mx0 = fmaxf(mx0, __shfl_xor_sync(0xffffffffu, mx0, 1));
        mx0 = fmaxf(mx0, __shfl_xor_sync(0xffffffffu, mx0, 2));
        mx1 = fmaxf(mx1, __shfl_xor_sync(0xffffffffu, mx1, 1));
        mx1 = fmaxf(mx1, __shfl_xor_sync(0xffffffffu, mx1, 2));
        float mn0 = fmaxf(m0, mx0), mn1 = fmaxf(m1, mx1);
        float al0 = __expf(m0 - mn0), al1 = __expf(m1 - mn1);
        float sum0 = 0.f, sum1 = 0.f;
#pragma unroll
        for (int nf = 0; nf < 8; nf++) {
            s[nf][0] = __expf(s[nf][0] - mn0);
            s[nf][1] = __expf(s[nf][1] - mn0);
            s[nf][2] = __expf(s[nf][2] - mn1);
            s[nf][3] = __expf(s[nf][3] - mn1);
            sum0 += s[nf][0] + s[nf][1];
            sum1 += s[nf][2] + s[nf][3];
        }
        sum0 += __shfl_xor_sync(0xffffffffu, sum0, 1);
        sum0 += __shfl_xor_sync(0xffffffffu, sum0, 2);
        sum1 += __shfl_xor_sync(0xffffffffu, sum1, 1);
        sum1 += __shfl_xor_sync(0xffffffffu, sum1, 2);
        l0 = l0 * al0 + sum0;  m0 = mn0;
        l1 = l1 * al1 + sum1;  m1 = mn1;
#pragma unroll
        for (int nf = 0; nf < 8; nf++) {
            o[nf][0] *= al0; o[nf][1] *= al0;
            o[nf][2] *= al1; o[nf][3] *= al1;
        }

        uint32_t phi[4][4], plo[4][4];
#pragma unroll
        for (int kc = 0; kc < 4; kc++) {
            split_pair(s[2 * kc][0],     s[2 * kc][1],     phi[kc][0], plo[kc][0]);
            split_pair(s[2 * kc][2],     s[2 * kc][3],     phi[kc][1], plo[kc][1]);
            split_pair(s[2 * kc + 1][0], s[2 * kc + 1][1], phi[kc][2], plo[kc][2]);
            split_pair(s[2 * kc + 1][2], s[2 * kc + 1][3], phi[kc][3], plo[kc][3]);
        }

#pragma unroll
        for (int kc = 0; kc < 4; kc++) {
            uint32_t vfh[4][4], vfl[4][4];
#pragma unroll
            for (int g = 0; g < 4; g++) {
                int hw = (16 * g + b_row) * FP + kc * 16 + b_k;
                ldsm_x4(vfh[g], sbase + 2 * (FV_HI + hw));
                ldsm_x4(vfl[g], sbase + 2 * (FV_LO + hw));
            }
#pragma unroll
            for (int g = 0; g < 4; g++) {
                mma16816(o[2 * g],     phi[kc], &vfh[g][0]);
                mma16816(o[2 * g],     phi[kc], &vfl[g][0]);
                mma16816(o[2 * g],     plo[kc], &vfh[g][0]);
                mma16816(o[2 * g + 1], phi[kc], &vfh[g][2]);
                mma16816(o[2 * g + 1], phi[kc], &vfl[g][2]);
                mma16816(o[2 * g + 1], plo[kc], &vfh[g][2]);
            }
        }
        __syncthreads();
    }

    // ---- epilogue: normalize + split + write bf16 hi/lo directly ----
    float inv0 = 1.0f / l0, inv1 = 1.0f / l1;
    int row0 = q0 + wm * 16 + gq;
    size_t base0 = ((size_t)b * T_ + row0) * (H_ * D_) + h * D_;
    size_t base1 = base0 + (size_t)8 * (H_ * D_);
    uint16_t* OhP = (uint16_t*)Oh;
    uint16_t* OlP = (uint16_t*)Ol;
#pragma unroll
    for (int nf = 0; nf < 8; nf++) {
        int c = nf * 8 + 2 * qt;
        uint32_t hw, lw;
        split_pair(o[nf][0] * inv0, o[nf][1] * inv0, hw, lw);
        *(uint32_t*)(OhP + base0 + c) = hw;
        *(uint32_t*)(OlP + base0 + c) = lw;
        split_pair(o[nf][2] * inv1, o[nf][3] * inv1, hw, lw);
        *(uint32_t*)(OhP + base1 + c) = hw;
        *(uint32_t*)(OlP + base1 + c) = lw;
    }
}

// ===========================================================================
extern "C" void kernel_launch(void* const* d_in, const int* in_sizes, int n_in,
                              void* d_out, int out_size)
{
    const float* x    = (const float*)d_in[0];
    const float* cosT = (const float*)d_in[1];
    const float* sinT = (const float*)d_in[2];
    const float* wq   = (const float*)d_in[3];
    const float* wk   = (const float*)d_in[4];
    const float* wv   = (const float*)d_in[5];
    const float* wo   = (const float*)d_in[6];

    float* out   = (float*)d_out;
    float* out_k = out   + (size_t)B_ * T_ * C_;
    float* out_v = out_k + (size_t)B_ * HK_ * T_ * D_;

    float *qraw, *kraw, *vraw;
    cudaGetSymbolAddress((void**)&qraw, g_qraw);
    cudaGetSymbolAddress((void**)&kraw, g_kraw);
    cudaGetSymbolAddress((void**)&vraw, g_vraw);

    __nv_bfloat16 *xh, *xl, *oh, *ol, *wqh, *wql, *wkh, *wkl, *wvh, *wvl, *woh, *wol;
    __nv_bfloat16 *qh, *ql, *kh, *kl, *vh, *vl;
    cudaGetSymbolAddress((void**)&xh, g_xh);   cudaGetSymbolAddress((void**)&xl, g_xl);
    cudaGetSymbolAddress((void**)&oh, g_oh);   cudaGetSymbolAddress((void**)&ol, g_ol);
    cudaGetSymbolAddress((void**)&wqh, g_wqh); cudaGetSymbolAddress((void**)&wql, g_wql);
    cudaGetSymbolAddress((void**)&wkh, g_wkh); cudaGetSymbolAddress((void**)&wkl, g_wkl);
    cudaGetSymbolAddress((void**)&wvh, g_wvh); cudaGetSymbolAddress((void**)&wvl, g_wvl);
    cudaGetSymbolAddress((void**)&woh, g_woh); cudaGetSymbolAddress((void**)&wol, g_wol);
    cudaGetSymbolAddress((void**)&qh, g_qh);   cudaGetSymbolAddress((void**)&ql, g_ql);
    cudaGetSymbolAddress((void**)&kh, g_kh);   cudaGetSymbolAddress((void**)&kl, g_kl);
    cudaGetSymbolAddress((void**)&vh, g_vh);   cudaGetSymbolAddress((void**)&vl, g_vl);

    cudaFuncSetAttribute(gemm_proj,
                         cudaFuncAttributeMaxDynamicSharedMemorySize, GEMM_SMEM);
    cudaFuncSetAttribute(gemm_out,
                         cudaFuncAttributeMaxDynamicSharedMemorySize, GEMM_SMEM);

    // ---- pre-split inputs into bf16 hi/lo ----
    {
        int nx = (MROWS * C_) / 8;
        int nw = ((H_ * D_) * C_) / 8;
        int ns = ((HK_ * D_) * C_) / 8;
        split_f32<<<(nx + 255) / 256, 256>>>(x,  xh,  xl,  nx);
        split_f32<<<(nw + 255) / 256, 256>>>(wq, wqh, wql, nw);
        split_f32<<<(ns + 255) / 256, 256>>>(wk, wkh, wkl, ns);
        split_f32<<<(ns + 255) / 256, 256>>>(wv, wvh, wvl, ns);
        split_f32<<<(nw + 255) / 256, 256>>>(wo, woh, wol, nw);
    }

    // ---- fused q/k/v projections (one launch) ----
    gemm_proj<<<dim3(20, MROWS / 128), 256, GEMM_SMEM>>>(
        xh, xl, wqh, wql, wkh, wkl, wvh, wvl, qraw, kraw, vraw);

    // ---- RoPE + layout + split ----
    {
        long long pq = (long long)B_ * T_ * H_ * (D_ / 2);
        long long pk = (long long)B_ * T_ * HK_ * (D_ / 2);
        rope_scatter2<<<(unsigned)((pq + 255) / 256), 256>>>(
            qraw, cosT, sinT, (float*)nullptr, qh, ql, H_, 0.125f, 1);
        rope_scatter2<<<(unsigned)((pk + 255) / 256), 256>>>(
            kraw, cosT, sinT, out_k, kh, kl, HK_, 1.0f, 1);
        rope_scatter2<<<(unsigned)((pk + 255) / 256), 256>>>(
            vraw, cosT, sinT, out_v, vh, vl, HK_, 1.0f, 0);
    }

    // ---- flash attention (writes pre-split oh/ol) ----
    flash_mma<<<dim3(T_ / 64, B_ * H_), 128>>>(qh, ql, kh, kl, vh, vl, oh, ol);

    // ---- output projection ----
    gemm_out<<<dim3(C_ / 128, MROWS / 128), 256, GEMM_SMEM>>>(oh, ol, woh, wol, out);
}